// round 3
// baseline (speedup 1.0000x reference)
#include <cuda_runtime.h>
#include <math.h>
#include <stdint.h>

// ---------------- problem constants ----------------
#define B_   2
#define S_   512
#define T_   1024          // B*S tokens
#define H_   1024
#define NH_  16
#define HD_  64
#define E_   32
#define D_   8
#define EPD_ 4
#define K_   6
#define KD_  3
#define I_   1536
#define EPS_ 1e-5f
#define TK_  (T_*K_)       // 6144 assignments

// ---------------- device scratch (static, allowed) ----------------
__device__ float g_qkv [T_*3*H_];     // 12.6 MB
__device__ float g_attn[T_*H_];
__device__ float g_tmp [T_*H_];
__device__ float g_h1  [T_*H_];
__device__ float g_sgu [T_*2*I_];     // shared-expert gate/up
__device__ float g_sact[T_*I_];
__device__ float g_sout[T_*H_];
__device__ float g_rgu [TK_*2*I_];    // 75.5 MB
__device__ float g_ract[TK_*I_];      // 37.7 MB
__device__ float g_rdwn[TK_*H_];      // 25 MB, indexed by slot=t*K+k

__device__ float g_Pi  [E_];
__device__ float g_comm[D_];
__device__ int   g_cnt [E_];
__device__ int   g_off [E_];
__device__ int   g_cur [E_];
__device__ int   g_sel_e[TK_];
__device__ float g_sel_w[TK_];
__device__ int   g_ltok [TK_];        // token per list position
__device__ int   g_lslot[TK_];        // slot per list position
__device__ float g_lw   [TK_];        // weight per list position

// ---------------- small helpers ----------------
__device__ __forceinline__ float block_sum256(float v) {
    __shared__ float red[8];
    __shared__ float tot;
    #pragma unroll
    for (int o = 16; o; o >>= 1) v += __shfl_xor_sync(0xffffffffu, v, o);
    if ((threadIdx.x & 31) == 0) red[threadIdx.x >> 5] = v;
    __syncthreads();
    if (threadIdx.x < 8) {
        float s = red[threadIdx.x];
        #pragma unroll
        for (int o = 4; o; o >>= 1) s += __shfl_xor_sync(0xffu, s, o);
        if (threadIdx.x == 0) tot = s;
    }
    __syncthreads();
    return tot;
}

// ---------------- generic SGEMM: C[M,N] = A[M,Kd] @ B[Kd,N] (+C if accum) ----
// Requires M%64==0, N%64==0, Kd%16==0. grid=(N/64, M/64), block=256.
__global__ __launch_bounds__(256)
void sgemm_nn(const float* __restrict__ A, const float* __restrict__ Bm,
              float* __restrict__ C, int Kd, int N, int accum) {
    __shared__ float As[16][64];
    __shared__ float Bs[16][64];
    const int tid = threadIdx.x;
    const int m0 = blockIdx.y * 64, n0 = blockIdx.x * 64;
    const int ar = tid >> 2, ac = (tid & 3) * 4;
    const int br = tid >> 4, bc = (tid & 15) * 4;
    const int ty = tid >> 4, tx = tid & 15;
    const float* Ap = A + (size_t)(m0 + ar) * Kd + ac;
    const float* Bp = Bm + (size_t)br * N + n0 + bc;
    float acc[4][4] = {};
    for (int k0 = 0; k0 < Kd; k0 += 16) {
        float4 a4 = *(const float4*)(Ap + k0);
        float4 b4 = *(const float4*)(Bp + (size_t)k0 * N);
        As[ac + 0][ar] = a4.x; As[ac + 1][ar] = a4.y;
        As[ac + 2][ar] = a4.z; As[ac + 3][ar] = a4.w;
        *(float4*)&Bs[br][bc] = b4;
        __syncthreads();
        #pragma unroll
        for (int kk = 0; kk < 16; kk++) {
            float4 av = *(const float4*)&As[kk][ty * 4];
            float4 bv = *(const float4*)&Bs[kk][tx * 4];
            acc[0][0] += av.x * bv.x; acc[0][1] += av.x * bv.y; acc[0][2] += av.x * bv.z; acc[0][3] += av.x * bv.w;
            acc[1][0] += av.y * bv.x; acc[1][1] += av.y * bv.y; acc[1][2] += av.y * bv.z; acc[1][3] += av.y * bv.w;
            acc[2][0] += av.z * bv.x; acc[2][1] += av.z * bv.y; acc[2][2] += av.z * bv.z; acc[2][3] += av.z * bv.w;
            acc[3][0] += av.w * bv.x; acc[3][1] += av.w * bv.y; acc[3][2] += av.w * bv.z; acc[3][3] += av.w * bv.w;
        }
        __syncthreads();
    }
    #pragma unroll
    for (int i = 0; i < 4; i++) {
        float* Cp = C + (size_t)(m0 + ty * 4 + i) * N + n0 + tx * 4;
        float4 v = make_float4(acc[i][0], acc[i][1], acc[i][2], acc[i][3]);
        if (accum) { float4 o = *(float4*)Cp; v.x += o.x; v.y += o.y; v.z += o.z; v.w += o.w; }
        *(float4*)Cp = v;
    }
}

// ---------------- flash attention: reads g_qkv, writes g_attn --------------
// grid=(S/64, NH, B), block=256. Q tile 64 rows, K/V tiles 32 rows.
__global__ __launch_bounds__(256)
void flash_attn() {
    __shared__ float Qs[64][68];
    __shared__ float Ks[32][68];
    __shared__ float Vs[32][68];
    __shared__ float Ps[64][36];
    const int q0 = blockIdx.x * 64;
    const int h  = blockIdx.y;
    const int b  = blockIdx.z;
    const int tid = threadIdx.x;
    const size_t rs = 3 * H_;
    const float* qb = g_qkv + (size_t)b * S_ * rs + (size_t)h * HD_;
    const float* kb = qb + H_;
    const float* vb = qb + 2 * H_;
    const float scale = 0.125f;   // 1/sqrt(64)
    for (int i = tid; i < 64 * 64; i += 256) {
        int r = i >> 6, d = i & 63;
        Qs[r][d] = qb[(size_t)(q0 + r) * rs + d] * scale;
    }
    const int r  = tid >> 2;
    const int c4 = tid & 3;
    float m_i = -1e30f, l_i = 0.f;
    float acc[16];
    #pragma unroll
    for (int i = 0; i < 16; i++) acc[i] = 0.f;
    __syncthreads();
    for (int kt = 0; kt < S_; kt += 32) {
        for (int i = tid; i < 32 * 64; i += 256) {
            int rr = i >> 6, d = i & 63;
            Ks[rr][d] = kb[(size_t)(kt + rr) * rs + d];
            Vs[rr][d] = vb[(size_t)(kt + rr) * rs + d];
        }
        __syncthreads();
        float sc[8];
        float mx = -1e30f;
        const float4* qrow = (const float4*)&Qs[r][0];
        #pragma unroll
        for (int jj = 0; jj < 8; jj++) {
            int j = c4 * 8 + jj;
            const float4* krow = (const float4*)&Ks[j][0];
            float sv = 0.f;
            #pragma unroll
            for (int dv = 0; dv < 16; dv++) {
                float4 a = qrow[dv], bq = krow[dv];
                sv += a.x * bq.x + a.y * bq.y + a.z * bq.z + a.w * bq.w;
            }
            sc[jj] = sv; mx = fmaxf(mx, sv);
        }
        mx = fmaxf(mx, __shfl_xor_sync(0xffffffffu, mx, 1));
        mx = fmaxf(mx, __shfl_xor_sync(0xffffffffu, mx, 2));
        float m_new = fmaxf(m_i, mx);
        float alpha = expf(m_i - m_new);
        float psum = 0.f;
        #pragma unroll
        for (int jj = 0; jj < 8; jj++) {
            float p = expf(sc[jj] - m_new);
            Ps[r][c4 * 8 + jj] = p;
            psum += p;
        }
        psum += __shfl_xor_sync(0xffffffffu, psum, 1);
        psum += __shfl_xor_sync(0xffffffffu, psum, 2);
        l_i = l_i * alpha + psum;
        m_i = m_new;
        #pragma unroll
        for (int i = 0; i < 16; i++) acc[i] *= alpha;
        __syncwarp();
        #pragma unroll
        for (int i = 0; i < 16; i++) {
            int d = c4 * 16 + i;
            float s = 0.f;
            #pragma unroll 8
            for (int j = 0; j < 32; j++) s += Ps[r][j] * Vs[j][d];
            acc[i] += s;
        }
        __syncthreads();
    }
    float inv = 1.f / l_i;
    float* ob = g_attn + (size_t)((b * S_ + q0 + r)) * H_ + (size_t)h * HD_;
    #pragma unroll
    for (int i = 0; i < 16; i++) ob[c4 * 16 + i] = acc[i] * inv;
}

// ---------------- residual + rmsnorm: o = rmsnorm(a + b) -------------------
__global__ __launch_bounds__(256)
void resid_rms(const float* __restrict__ a, const float* __restrict__ b,
               float* __restrict__ o) {
    const int t = blockIdx.x;
    float v[4]; float ss = 0.f;
    #pragma unroll
    for (int i = 0; i < 4; i++) {
        int j = i * 256 + threadIdx.x;
        float s = a[(size_t)t * H_ + j] + b[(size_t)t * H_ + j];
        v[i] = s; ss += s * s;
    }
    ss = block_sum256(ss);
    float inv = rsqrtf(ss * (1.f / H_) + EPS_);
    #pragma unroll
    for (int i = 0; i < 4; i++) {
        int j = i * 256 + threadIdx.x;
        o[(size_t)t * H_ + j] = v[i] * inv;
    }
}

// ---------------- swiglu activation: act = silu(g)*u -----------------------
__global__ __launch_bounds__(256)
void swiglu_act(const float* __restrict__ gu, float* __restrict__ act, int rows) {
    int i = blockIdx.x * 256 + threadIdx.x;
    int total = rows * I_;
    if (i >= total) return;
    int r = i / I_, c = i - r * I_;
    float g = gu[(size_t)r * (2 * I_) + c];
    float u = gu[(size_t)r * (2 * I_) + I_ + c];
    act[(size_t)r * I_ + c] = (g / (1.f + expf(-g))) * u;
}

// ---------------- routing ---------------------------------------------------
__global__ void zero_small() {
    int i = threadIdx.x;
    if (i < E_) { g_Pi[i] = 0.f; g_cnt[i] = 0; }
    if (i < D_)   g_comm[i] = 0.f;
}

__global__ void routing_kernel(const float* __restrict__ Wr) {
    const int t = blockIdx.x;
    const int e = threadIdx.x;   // 32 threads
    const float* xr = g_h1 + (size_t)t * H_;
    float logit = 0.f;
    for (int j = 0; j < H_; j++) logit += xr[j] * Wr[(size_t)j * E_ + e];
    float m = logit;
    #pragma unroll
    for (int o = 16; o; o >>= 1) m = fmaxf(m, __shfl_xor_sync(0xffffffffu, m, o));
    float ex = expf(logit - m);
    float s = ex;
    #pragma unroll
    for (int o = 16; o; o >>= 1) s += __shfl_xor_sync(0xffffffffu, s, o);
    float prob = ex / s;
    atomicAdd(&g_Pi[e], prob);
    __shared__ float sp[E_];
    sp[e] = prob;
    __syncwarp();
    if (e == 0) {
        float ds[D_];
        #pragma unroll
        for (int d = 0; d < D_; d++)
            ds[d] = sp[4 * d] + sp[4 * d + 1] + sp[4 * d + 2] + sp[4 * d + 3];
        bool dsel[D_] = {};
        for (int rsel = 0; rsel < KD_; rsel++) {
            int best = -1; float bv = -1e30f;
            for (int d = 0; d < D_; d++)
                if (!dsel[d] && ds[d] > bv) { bv = ds[d]; best = d; }
            dsel[best] = true;
        }
        float masked[E_];
        #pragma unroll
        for (int i = 0; i < E_; i++)
            masked[i] = dsel[i >> 2] ? sp[i] : -1e30f;
        int   iv[K_]; float wv[K_];
        for (int rsel = 0; rsel < K_; rsel++) {
            int best = 0; float bv = -1e31f;
            for (int i = 0; i < E_; i++)
                if (masked[i] > bv) { bv = masked[i]; best = i; }
            iv[rsel] = best; wv[rsel] = bv;
            masked[best] = -1e31f;
        }
        float mm = wv[0];                 // largest, extraction is descending
        float ssum = 0.f;
        #pragma unroll
        for (int rsel = 0; rsel < K_; rsel++) { wv[rsel] = expf(wv[rsel] - mm); ssum += wv[rsel]; }
        bool hit[D_] = {};
        #pragma unroll
        for (int rsel = 0; rsel < K_; rsel++) hit[iv[rsel] >> 2] = true;
        for (int d = 0; d < D_; d++)
            if (hit[d]) atomicAdd(&g_comm[d], 1.0f);
        #pragma unroll
        for (int rsel = 0; rsel < K_; rsel++) {
            int idx = t * K_ + rsel;
            g_sel_e[idx] = iv[rsel];
            g_sel_w[idx] = wv[rsel] / ssum;
            atomicAdd(&g_cnt[iv[rsel]], 1);
        }
    }
}

__global__ void offsets_kernel() {
    if (threadIdx.x == 0) {
        int s = 0;
        for (int e = 0; e < E_; e++) { g_off[e] = s; g_cur[e] = s; s += g_cnt[e]; }
    }
}

__global__ void scatter_kernel() {
    int i = blockIdx.x * 256 + threadIdx.x;
    if (i >= TK_) return;
    int e = g_sel_e[i];
    int pos = atomicAdd(&g_cur[e], 1);
    g_ltok[pos]  = i / K_;
    g_lslot[pos] = i;
    g_lw[pos]    = g_sel_w[i];
}

// ---------------- routed expert GEMMs --------------------------------------
// up: rows gathered from g_h1 by token list; C rows contiguous in list order.
// grid=(2*I/64, T/64, E), block=256.
__global__ __launch_bounds__(256)
void sgemm_up_routed(const float* __restrict__ Wgu) {
    const int e = blockIdx.z;
    const int cnt = g_cnt[e];
    const int m0 = blockIdx.y * 64;
    if (m0 >= cnt) return;
    const int off = g_off[e];
    const int n0 = blockIdx.x * 64;
    const float* __restrict__ Bm = Wgu + (size_t)e * H_ * 2 * I_;
    __shared__ float As[16][64];
    __shared__ float Bs[16][64];
    const int tid = threadIdx.x;
    const int ar = tid >> 2, ac = (tid & 3) * 4;
    const int br = tid >> 4, bc = (tid & 15) * 4;
    const int ty = tid >> 4, tx = tid & 15;
    const bool aok = (m0 + ar) < cnt;
    const float* Ap = g_h1;
    if (aok) Ap = g_h1 + (size_t)g_ltok[off + m0 + ar] * H_ + ac;
    const float* Bp = Bm + (size_t)br * (2 * I_) + n0 + bc;
    float acc[4][4] = {};
    for (int k0 = 0; k0 < H_; k0 += 16) {
        float4 a4 = aok ? *(const float4*)(Ap + k0) : make_float4(0.f, 0.f, 0.f, 0.f);
        float4 b4 = *(const float4*)(Bp + (size_t)k0 * (2 * I_));
        As[ac + 0][ar] = a4.x; As[ac + 1][ar] = a4.y;
        As[ac + 2][ar] = a4.z; As[ac + 3][ar] = a4.w;
        *(float4*)&Bs[br][bc] = b4;
        __syncthreads();
        #pragma unroll
        for (int kk = 0; kk < 16; kk++) {
            float4 av = *(const float4*)&As[kk][ty * 4];
            float4 bv = *(const float4*)&Bs[kk][tx * 4];
            acc[0][0] += av.x * bv.x; acc[0][1] += av.x * bv.y; acc[0][2] += av.x * bv.z; acc[0][3] += av.x * bv.w;
            acc[1][0] += av.y * bv.x; acc[1][1] += av.y * bv.y; acc[1][2] += av.y * bv.z; acc[1][3] += av.y * bv.w;
            acc[2][0] += av.z * bv.x; acc[2][1] += av.z * bv.y; acc[2][2] += av.z * bv.z; acc[2][3] += av.z * bv.w;
            acc[3][0] += av.w * bv.x; acc[3][1] += av.w * bv.y; acc[3][2] += av.w * bv.z; acc[3][3] += av.w * bv.w;
        }
        __syncthreads();
    }
    #pragma unroll
    for (int i = 0; i < 4; i++) {
        int row = m0 + ty * 4 + i;
        if (row < cnt) {
            float* Cp = g_rgu + (size_t)(off + row) * (2 * I_) + n0 + tx * 4;
            Cp[0] = acc[i][0]; Cp[1] = acc[i][1]; Cp[2] = acc[i][2]; Cp[3] = acc[i][3];
        }
    }
}

// down: A rows contiguous (g_ract at offset), scatter to slot with weight.
// grid=(H/64, T/64, E), block=256.
__global__ __launch_bounds__(256)
void sgemm_down_routed(const float* __restrict__ Wd) {
    const int e = blockIdx.z;
    const int cnt = g_cnt[e];
    const int m0 = blockIdx.y * 64;
    if (m0 >= cnt) return;
    const int off = g_off[e];
    const int n0 = blockIdx.x * 64;
    const float* __restrict__ Bm = Wd + (size_t)e * I_ * H_;
    __shared__ float As[16][64];
    __shared__ float Bs[16][64];
    const int tid = threadIdx.x;
    const int ar = tid >> 2, ac = (tid & 3) * 4;
    const int br = tid >> 4, bc = (tid & 15) * 4;
    const int ty = tid >> 4, tx = tid & 15;
    const bool aok = (m0 + ar) < cnt;
    const float* Ap = g_ract + (size_t)(off + (aok ? m0 + ar : 0)) * I_ + ac;
    const float* Bp = Bm + (size_t)br * H_ + n0 + bc;
    float acc[4][4] = {};
    for (int k0 = 0; k0 < I_; k0 += 16) {
        float4 a4 = aok ? *(const float4*)(Ap + k0) : make_float4(0.f, 0.f, 0.f, 0.f);
        float4 b4 = *(const float4*)(Bp + (size_t)k0 * H_);
        As[ac + 0][ar] = a4.x; As[ac + 1][ar] = a4.y;
        As[ac + 2][ar] = a4.z; As[ac + 3][ar] = a4.w;
        *(float4*)&Bs[br][bc] = b4;
        __syncthreads();
        #pragma unroll
        for (int kk = 0; kk < 16; kk++) {
            float4 av = *(const float4*)&As[kk][ty * 4];
            float4 bv = *(const float4*)&Bs[kk][tx * 4];
            acc[0][0] += av.x * bv.x; acc[0][1] += av.x * bv.y; acc[0][2] += av.x * bv.z; acc[0][3] += av.x * bv.w;
            acc[1][0] += av.y * bv.x; acc[1][1] += av.y * bv.y; acc[1][2] += av.y * bv.z; acc[1][3] += av.y * bv.w;
            acc[2][0] += av.z * bv.x; acc[2][1] += av.z * bv.y; acc[2][2] += av.z * bv.z; acc[2][3] += av.z * bv.w;
            acc[3][0] += av.w * bv.x; acc[3][1] += av.w * bv.y; acc[3][2] += av.w * bv.z; acc[3][3] += av.w * bv.w;
        }
        __syncthreads();
    }
    #pragma unroll
    for (int i = 0; i < 4; i++) {
        int row = m0 + ty * 4 + i;
        if (row < cnt) {
            int   slot = g_lslot[off + row];
            float w    = g_lw[off + row];
            float* Cp = g_rdwn + (size_t)slot * H_ + n0 + tx * 4;
            Cp[0] = w * acc[i][0]; Cp[1] = w * acc[i][1];
            Cp[2] = w * acc[i][2]; Cp[3] = w * acc[i][3];
        }
    }
}

// ---------------- final combine + rmsnorm -----------------------------------
__global__ __launch_bounds__(256)
void final_kernel(float* __restrict__ out) {
    const int t = blockIdx.x;
    float v[4]; float ss = 0.f;
    #pragma unroll
    for (int i = 0; i < 4; i++) {
        int j = i * 256 + threadIdx.x;
        float s = g_h1[(size_t)t * H_ + j] + g_sout[(size_t)t * H_ + j];
        #pragma unroll
        for (int k = 0; k < K_; k++)
            s += g_rdwn[(size_t)(t * K_ + k) * H_ + j];
        v[i] = s; ss += s * s;
    }
    ss = block_sum256(ss);
    float inv = rsqrtf(ss * (1.f / H_) + EPS_);
    #pragma unroll
    for (int i = 0; i < 4; i++) {
        int j = i * 256 + threadIdx.x;
        out[(size_t)t * H_ + j] = v[i] * inv;
    }
}

__global__ void aux_kernel(float* out, int out_size) {
    if (out_size <= T_ * H_) return;
    const float fTK = (float)TK_ + 1e-10f;
    float fi[E_], Pi[E_];
    float s1 = 0.f;
    for (int e = 0; e < E_; e++) {
        fi[e] = (float)g_cnt[e] / fTK;
        Pi[e] = g_Pi[e] / (float)T_;
        s1 += fi[e] * Pi[e];
    }
    float eb = fminf(s1 * 0.003f, 10.f);
    float dP[D_];
    float s2 = 0.f;
    for (int d = 0; d < D_; d++) {
        float df = (fi[4*d] + fi[4*d+1] + fi[4*d+2] + fi[4*d+3]) * 0.25f;
        dP[d]    = Pi[4*d] + Pi[4*d+1] + Pi[4*d+2] + Pi[4*d+3];
        s2 += df * dP[d];
    }
    float db = fminf(s2 * 0.05f, 10.f);
    float s3 = 0.f;
    for (int d = 0; d < D_; d++) {
        float fc = g_comm[d] / ((float)(T_ * KD_) + 1e-10f);
        s3 += fc * dP[d];
    }
    float cb = fminf(s3 * 0.02f, 10.f);
    out[T_ * H_] = eb + db + cb;
}

// ---------------- host driver ------------------------------------------------
extern "C" void kernel_launch(void* const* d_in, const int* in_sizes, int n_in,
                              void* d_out, int out_size) {
    const float* x     = (const float*)d_in[0];
    const float* Wqkv  = (const float*)d_in[1];
    const float* Wo    = (const float*)d_in[2];
    const float* Wgu_s = (const float*)d_in[3];
    const float* Wd_s  = (const float*)d_in[4];
    const float* Wr    = (const float*)d_in[5];
    const float* Wgu   = (const float*)d_in[6];
    const float* Wd    = (const float*)d_in[7];
    float* out = (float*)d_out;

    float *p_qkv, *p_attn, *p_tmp, *p_h1, *p_sgu, *p_sact, *p_sout, *p_rgu, *p_ract;
    cudaGetSymbolAddress((void**)&p_qkv,  g_qkv);
    cudaGetSymbolAddress((void**)&p_attn, g_attn);
    cudaGetSymbolAddress((void**)&p_tmp,  g_tmp);
    cudaGetSymbolAddress((void**)&p_h1,   g_h1);
    cudaGetSymbolAddress((void**)&p_sgu,  g_sgu);
    cudaGetSymbolAddress((void**)&p_sact, g_sact);
    cudaGetSymbolAddress((void**)&p_sout, g_sout);
    cudaGetSymbolAddress((void**)&p_rgu,  g_rgu);
    cudaGetSymbolAddress((void**)&p_ract, g_ract);

    zero_small<<<1, 64>>>();

    // qkv = x @ Wqkv  (1024 x 1024 x 3072)
    sgemm_nn<<<dim3(3 * H_ / 64, T_ / 64), 256>>>(x, Wqkv, p_qkv, H_, 3 * H_, 0);

    // attention
    flash_attn<<<dim3(S_ / 64, NH_, B_), 256>>>();

    // proj = attn @ Wo, h1 = rmsnorm(x + proj)
    sgemm_nn<<<dim3(H_ / 64, T_ / 64), 256>>>(p_attn, Wo, p_tmp, H_, H_, 0);
    resid_rms<<<T_, 256>>>(x, p_tmp, p_h1);

    // shared experts (2), accumulate second into g_sout
    for (int e = 0; e < 2; e++) {
        sgemm_nn<<<dim3(2 * I_ / 64, T_ / 64), 256>>>(
            p_h1, Wgu_s + (size_t)e * H_ * 2 * I_, p_sgu, H_, 2 * I_, 0);
        swiglu_act<<<(T_ * I_ + 255) / 256, 256>>>(p_sgu, p_sact, T_);
        sgemm_nn<<<dim3(H_ / 64, T_ / 64), 256>>>(
            p_sact, Wd_s + (size_t)e * I_ * H_, p_sout, I_, H_, e);
    }

    // routing + sparse dispatch
    routing_kernel<<<T_, 32>>>(Wr);
    offsets_kernel<<<1, 32>>>();
    scatter_kernel<<<(TK_ + 255) / 256, 256>>>();

    // routed up-proj (gathered), activation, down-proj (scattered, weighted)
    sgemm_up_routed<<<dim3(2 * I_ / 64, T_ / 64, E_), 256>>>(Wgu);
    swiglu_act<<<(TK_ * I_ + 255) / 256, 256>>>(p_rgu, p_ract, TK_);
    sgemm_down_routed<<<dim3(H_ / 64, T_ / 64, E_), 256>>>(Wd);

    // final residual + rmsnorm + aux
    final_kernel<<<T_, 256>>>(out);
    aux_kernel<<<1, 1>>>(out, out_size);
}

// round 4
// speedup vs baseline: 1.0803x; 1.0803x over previous
#include <cuda_runtime.h>
#include <math.h>
#include <stdint.h>

// ---------------- problem constants ----------------
#define B_   2
#define S_   512
#define T_   1024          // B*S tokens
#define H_   1024
#define NH_  16
#define HD_  64
#define E_   32
#define D_   8
#define K_   6
#define KD_  3
#define I_   1536
#define EPS_ 1e-5f
#define TK_  (T_*K_)       // 6144 assignments

// ---------------- device scratch (static, allowed) ----------------
__device__ float g_qkv [T_*3*H_];
__device__ float g_attn[T_*H_];
__device__ float g_tmp [T_*H_];
__device__ float g_h1  [T_*H_];
__device__ float g_sgu [T_*2*I_];     // shared-expert gate/up
__device__ float g_sout[T_*H_];
__device__ float g_rgu [TK_*2*I_];    // routed gate/up (75.5 MB)
__device__ float g_rdwn[TK_*H_];      // per-slot routed output

__device__ float g_Pi  [E_];
__device__ float g_comm[D_];
__device__ int   g_cnt [E_];
__device__ int   g_off [E_];
__device__ int   g_cur [E_];
__device__ int   g_sel_e[TK_];
__device__ float g_sel_w[TK_];
__device__ int   g_ltok [TK_];
__device__ int   g_lslot[TK_];
__device__ float g_lw   [TK_];

// ---------------- f32x2 packed-FMA helpers (sm_103a FFMA2 pipe) -------------
__device__ __forceinline__ unsigned long long pk2(float lo, float hi) {
    unsigned long long r;
    asm("mov.b64 %0,{%1,%2};" : "=l"(r) : "f"(lo), "f"(hi));
    return r;
}
__device__ __forceinline__ float2 upk2(unsigned long long v) {
    float2 r;
    asm("mov.b64 {%0,%1},%2;" : "=f"(r.x), "=f"(r.y) : "l"(v));
    return r;
}
__device__ __forceinline__ void ffma2(unsigned long long& d,
                                      unsigned long long a,
                                      unsigned long long b) {
    asm("fma.rn.f32x2 %0,%1,%2,%0;" : "+l"(d) : "l"(a), "l"(b));
}
__device__ __forceinline__ float silu1(float g) { return g / (1.f + expf(-g)); }

__device__ __forceinline__ float block_sum256(float v) {
    __shared__ float red[8];
    __shared__ float tot;
    #pragma unroll
    for (int o = 16; o; o >>= 1) v += __shfl_xor_sync(0xffffffffu, v, o);
    if ((threadIdx.x & 31) == 0) red[threadIdx.x >> 5] = v;
    __syncthreads();
    if (threadIdx.x < 8) {
        float s = red[threadIdx.x];
        #pragma unroll
        for (int o = 4; o; o >>= 1) s += __shfl_xor_sync(0xffu, s, o);
        if (threadIdx.x == 0) tot = s;
    }
    __syncthreads();
    return tot;
}

// ============================================================================
// 128x128 SGEMM, K-tile 16, double-buffered, 8x8 per thread via fma.rn.f32x2.
// Requires M%128==0, N%128==0, Kd%16==0. grid=(N/128, M/128), block=256.
// ============================================================================
__global__ __launch_bounds__(256)
void sgemm_nn128(const float* __restrict__ A, const float* __restrict__ Bm,
                 float* __restrict__ C, int Kd, int N, int accum) {
    __shared__ __align__(16) float As[2][16][132];
    __shared__ __align__(16) float Bs[2][16][132];
    const int tid = threadIdx.x;
    const int m0 = blockIdx.y * 128, n0 = blockIdx.x * 128;
    const int tx = tid & 15, ty = tid >> 4;

    unsigned long long acc[8][4];
    #pragma unroll
    for (int i = 0; i < 8; i++)
        #pragma unroll
        for (int j = 0; j < 4; j++) acc[i][j] = 0ull;

    // prologue: stage k-tile 0 into buf 0
    #pragma unroll
    for (int l = 0; l < 2; l++) {
        int idx = tid + l * 256;
        int r = idx >> 2, kc = (idx & 3) * 4;
        float4 v = *(const float4*)(A + (size_t)(m0 + r) * Kd + kc);
        As[0][kc + 0][r] = v.x; As[0][kc + 1][r] = v.y;
        As[0][kc + 2][r] = v.z; As[0][kc + 3][r] = v.w;
        int k = idx >> 5, nc = (idx & 31) * 4;
        *(float4*)&Bs[0][k][nc] = *(const float4*)(Bm + (size_t)k * N + n0 + nc);
    }
    __syncthreads();

    const int nK = Kd >> 4;
    int buf = 0;
    for (int kt = 0; kt < nK; kt++) {
        float4 pa[2], pb[2];
        const bool nxt = (kt + 1) < nK;
        if (nxt) {
            int k0 = (kt + 1) << 4;
            #pragma unroll
            for (int l = 0; l < 2; l++) {
                int idx = tid + l * 256;
                int r = idx >> 2, kc = (idx & 3) * 4;
                pa[l] = *(const float4*)(A + (size_t)(m0 + r) * Kd + k0 + kc);
                int k = idx >> 5, nc = (idx & 31) * 4;
                pb[l] = *(const float4*)(Bm + (size_t)(k0 + k) * N + n0 + nc);
            }
        }
        #pragma unroll
        for (int kk = 0; kk < 16; kk++) {
            float4 a0 = *(const float4*)&As[buf][kk][ty * 4];
            float4 a1 = *(const float4*)&As[buf][kk][64 + ty * 4];
            float4 b0 = *(const float4*)&Bs[buf][kk][tx * 4];
            float4 b1 = *(const float4*)&Bs[buf][kk][64 + tx * 4];
            unsigned long long bp0 = pk2(b0.x, b0.y), bp1 = pk2(b0.z, b0.w);
            unsigned long long bp2 = pk2(b1.x, b1.y), bp3 = pk2(b1.z, b1.w);
            float av[8] = {a0.x, a0.y, a0.z, a0.w, a1.x, a1.y, a1.z, a1.w};
            #pragma unroll
            for (int i = 0; i < 8; i++) {
                unsigned long long ad = pk2(av[i], av[i]);
                ffma2(acc[i][0], ad, bp0); ffma2(acc[i][1], ad, bp1);
                ffma2(acc[i][2], ad, bp2); ffma2(acc[i][3], ad, bp3);
            }
        }
        if (nxt) {
            int nb = buf ^ 1;
            #pragma unroll
            for (int l = 0; l < 2; l++) {
                int idx = tid + l * 256;
                int r = idx >> 2, kc = (idx & 3) * 4;
                As[nb][kc + 0][r] = pa[l].x; As[nb][kc + 1][r] = pa[l].y;
                As[nb][kc + 2][r] = pa[l].z; As[nb][kc + 3][r] = pa[l].w;
                int k = idx >> 5, nc = (idx & 31) * 4;
                *(float4*)&Bs[nb][k][nc] = pb[l];
            }
        }
        __syncthreads();
        buf ^= 1;
    }

    #pragma unroll
    for (int i = 0; i < 8; i++) {
        int row = m0 + ((i < 4) ? (ty * 4 + i) : (64 + ty * 4 + i - 4));
        float2 p0 = upk2(acc[i][0]), p1 = upk2(acc[i][1]);
        float2 p2 = upk2(acc[i][2]), p3 = upk2(acc[i][3]);
        float* c0 = C + (size_t)row * N + n0 + tx * 4;
        float* c1 = C + (size_t)row * N + n0 + 64 + tx * 4;
        float4 v0 = make_float4(p0.x, p0.y, p1.x, p1.y);
        float4 v1 = make_float4(p2.x, p2.y, p3.x, p3.y);
        if (accum) {
            float4 o0 = *(float4*)c0, o1 = *(float4*)c1;
            v0.x += o0.x; v0.y += o0.y; v0.z += o0.z; v0.w += o0.w;
            v1.x += o1.x; v1.y += o1.y; v1.z += o1.z; v1.w += o1.w;
        }
        *(float4*)c0 = v0; *(float4*)c1 = v1;
    }
}

// ============================================================================
// Shared-expert down GEMM with fused SwiGLU on the A side.
// A_eff[t][k] = silu(g_sgu[t][k]) * g_sgu[t][I_+k]; C = g_sout (accum flag).
// M=T_, N=H_, Kd=I_. grid=(H_/128, T_/128), block=256.
// ============================================================================
__global__ __launch_bounds__(256)
void sgemm_shared_down(const float* __restrict__ Wd_s, int accum) {
    __shared__ __align__(16) float As[2][16][132];
    __shared__ __align__(16) float Bs[2][16][132];
    const int tid = threadIdx.x;
    const int m0 = blockIdx.y * 128, n0 = blockIdx.x * 128;
    const int tx = tid & 15, ty = tid >> 4;
    const int N = H_, Kd = I_;

    unsigned long long acc[8][4];
    #pragma unroll
    for (int i = 0; i < 8; i++)
        #pragma unroll
        for (int j = 0; j < 4; j++) acc[i][j] = 0ull;

    #pragma unroll
    for (int l = 0; l < 2; l++) {
        int idx = tid + l * 256;
        int r = idx >> 2, kc = (idx & 3) * 4;
        const float* gp = g_sgu + (size_t)(m0 + r) * (2 * I_) + kc;
        float4 g = *(const float4*)gp, u = *(const float4*)(gp + I_);
        As[0][kc + 0][r] = silu1(g.x) * u.x; As[0][kc + 1][r] = silu1(g.y) * u.y;
        As[0][kc + 2][r] = silu1(g.z) * u.z; As[0][kc + 3][r] = silu1(g.w) * u.w;
        int k = idx >> 5, nc = (idx & 31) * 4;
        *(float4*)&Bs[0][k][nc] = *(const float4*)(Wd_s + (size_t)k * N + n0 + nc);
    }
    __syncthreads();

    const int nK = Kd >> 4;
    int buf = 0;
    for (int kt = 0; kt < nK; kt++) {
        float4 pa[2], pb[2];
        const bool nxt = (kt + 1) < nK;
        if (nxt) {
            int k0 = (kt + 1) << 4;
            #pragma unroll
            for (int l = 0; l < 2; l++) {
                int idx = tid + l * 256;
                int r = idx >> 2, kc = (idx & 3) * 4;
                const float* gp = g_sgu + (size_t)(m0 + r) * (2 * I_) + k0 + kc;
                float4 g = *(const float4*)gp, u = *(const float4*)(gp + I_);
                pa[l] = make_float4(silu1(g.x) * u.x, silu1(g.y) * u.y,
                                    silu1(g.z) * u.z, silu1(g.w) * u.w);
                int k = idx >> 5, nc = (idx & 31) * 4;
                pb[l] = *(const float4*)(Wd_s + (size_t)(k0 + k) * N + n0 + nc);
            }
        }
        #pragma unroll
        for (int kk = 0; kk < 16; kk++) {
            float4 a0 = *(const float4*)&As[buf][kk][ty * 4];
            float4 a1 = *(const float4*)&As[buf][kk][64 + ty * 4];
            float4 b0 = *(const float4*)&Bs[buf][kk][tx * 4];
            float4 b1 = *(const float4*)&Bs[buf][kk][64 + tx * 4];
            unsigned long long bp0 = pk2(b0.x, b0.y), bp1 = pk2(b0.z, b0.w);
            unsigned long long bp2 = pk2(b1.x, b1.y), bp3 = pk2(b1.z, b1.w);
            float av[8] = {a0.x, a0.y, a0.z, a0.w, a1.x, a1.y, a1.z, a1.w};
            #pragma unroll
            for (int i = 0; i < 8; i++) {
                unsigned long long ad = pk2(av[i], av[i]);
                ffma2(acc[i][0], ad, bp0); ffma2(acc[i][1], ad, bp1);
                ffma2(acc[i][2], ad, bp2); ffma2(acc[i][3], ad, bp3);
            }
        }
        if (nxt) {
            int nb = buf ^ 1;
            #pragma unroll
            for (int l = 0; l < 2; l++) {
                int idx = tid + l * 256;
                int r = idx >> 2, kc = (idx & 3) * 4;
                As[nb][kc + 0][r] = pa[l].x; As[nb][kc + 1][r] = pa[l].y;
                As[nb][kc + 2][r] = pa[l].z; As[nb][kc + 3][r] = pa[l].w;
                int k = idx >> 5, nc = (idx & 31) * 4;
                *(float4*)&Bs[nb][k][nc] = pb[l];
            }
        }
        __syncthreads();
        buf ^= 1;
    }

    #pragma unroll
    for (int i = 0; i < 8; i++) {
        int row = m0 + ((i < 4) ? (ty * 4 + i) : (64 + ty * 4 + i - 4));
        float2 p0 = upk2(acc[i][0]), p1 = upk2(acc[i][1]);
        float2 p2 = upk2(acc[i][2]), p3 = upk2(acc[i][3]);
        float* c0 = g_sout + (size_t)row * N + n0 + tx * 4;
        float* c1 = g_sout + (size_t)row * N + n0 + 64 + tx * 4;
        float4 v0 = make_float4(p0.x, p0.y, p1.x, p1.y);
        float4 v1 = make_float4(p2.x, p2.y, p3.x, p3.y);
        if (accum) {
            float4 o0 = *(float4*)c0, o1 = *(float4*)c1;
            v0.x += o0.x; v0.y += o0.y; v0.z += o0.z; v0.w += o0.w;
            v1.x += o1.x; v1.y += o1.y; v1.z += o1.z; v1.w += o1.w;
        }
        *(float4*)c0 = v0; *(float4*)c1 = v1;
    }
}

// ============================================================================
// Routed up GEMM: 64x128 tile, gathered A rows. grid=(2I/128, T/64, E).
// ============================================================================
__global__ __launch_bounds__(256)
void sgemm_up_r64(const float* __restrict__ Wgu) {
    const int e = blockIdx.z;
    const int cnt = g_cnt[e];
    const int m0 = blockIdx.y * 64;
    if (m0 >= cnt) return;
    const int off = g_off[e];
    const int n0 = blockIdx.x * 128;
    const float* __restrict__ Bm = Wgu + (size_t)e * H_ * 2 * I_;
    const int N = 2 * I_, Kd = H_;

    __shared__ __align__(16) float As[2][16][68];
    __shared__ __align__(16) float Bs[2][16][132];
    const int tid = threadIdx.x;
    const int tx = tid & 15, ty = tid >> 4;
    const int arow = tid >> 2, akc = (tid & 3) * 4;
    const int tok = (m0 + arow < cnt) ? g_ltok[off + m0 + arow] : -1;
    const float* Ap = (tok >= 0) ? (g_h1 + (size_t)tok * H_ + akc) : g_h1;

    unsigned long long acc[4][4];
    #pragma unroll
    for (int i = 0; i < 4; i++)
        #pragma unroll
        for (int j = 0; j < 4; j++) acc[i][j] = 0ull;

    {
        float4 v = (tok >= 0) ? *(const float4*)Ap : make_float4(0.f, 0.f, 0.f, 0.f);
        As[0][akc + 0][arow] = v.x; As[0][akc + 1][arow] = v.y;
        As[0][akc + 2][arow] = v.z; As[0][akc + 3][arow] = v.w;
        #pragma unroll
        for (int l = 0; l < 2; l++) {
            int idx = tid + l * 256;
            int k = idx >> 5, nc = (idx & 31) * 4;
            *(float4*)&Bs[0][k][nc] = *(const float4*)(Bm + (size_t)k * N + n0 + nc);
        }
    }
    __syncthreads();

    const int nK = Kd >> 4;
    int buf = 0;
    for (int kt = 0; kt < nK; kt++) {
        float4 pa, pb[2];
        const bool nxt = (kt + 1) < nK;
        if (nxt) {
            int k0 = (kt + 1) << 4;
            pa = (tok >= 0) ? *(const float4*)(Ap + k0) : make_float4(0.f, 0.f, 0.f, 0.f);
            #pragma unroll
            for (int l = 0; l < 2; l++) {
                int idx = tid + l * 256;
                int k = idx >> 5, nc = (idx & 31) * 4;
                pb[l] = *(const float4*)(Bm + (size_t)(k0 + k) * N + n0 + nc);
            }
        }
        #pragma unroll
        for (int kk = 0; kk < 16; kk++) {
            float4 a0 = *(const float4*)&As[buf][kk][ty * 4];
            float4 b0 = *(const float4*)&Bs[buf][kk][tx * 4];
            float4 b1 = *(const float4*)&Bs[buf][kk][64 + tx * 4];
            unsigned long long bp0 = pk2(b0.x, b0.y), bp1 = pk2(b0.z, b0.w);
            unsigned long long bp2 = pk2(b1.x, b1.y), bp3 = pk2(b1.z, b1.w);
            float av[4] = {a0.x, a0.y, a0.z, a0.w};
            #pragma unroll
            for (int i = 0; i < 4; i++) {
                unsigned long long ad = pk2(av[i], av[i]);
                ffma2(acc[i][0], ad, bp0); ffma2(acc[i][1], ad, bp1);
                ffma2(acc[i][2], ad, bp2); ffma2(acc[i][3], ad, bp3);
            }
        }
        if (nxt) {
            int nb = buf ^ 1;
            As[nb][akc + 0][arow] = pa.x; As[nb][akc + 1][arow] = pa.y;
            As[nb][akc + 2][arow] = pa.z; As[nb][akc + 3][arow] = pa.w;
            #pragma unroll
            for (int l = 0; l < 2; l++) {
                int idx = tid + l * 256;
                int k = idx >> 5, nc = (idx & 31) * 4;
                *(float4*)&Bs[nb][k][nc] = pb[l];
            }
        }
        __syncthreads();
        buf ^= 1;
    }

    #pragma unroll
    for (int i = 0; i < 4; i++) {
        int row = m0 + ty * 4 + i;
        if (row < cnt) {
            float2 p0 = upk2(acc[i][0]), p1 = upk2(acc[i][1]);
            float2 p2 = upk2(acc[i][2]), p3 = upk2(acc[i][3]);
            float* c0 = g_rgu + (size_t)(off + row) * N + n0 + tx * 4;
            float* c1 = c0 + 64;
            *(float4*)c0 = make_float4(p0.x, p0.y, p1.x, p1.y);
            *(float4*)c1 = make_float4(p2.x, p2.y, p3.x, p3.y);
        }
    }
}

// ============================================================================
// Routed down GEMM: 64x128 tile, fused SwiGLU on A, weighted scatter epilogue.
// grid=(H/128, T/64, E).
// ============================================================================
__global__ __launch_bounds__(256)
void sgemm_down_r64(const float* __restrict__ Wd) {
    const int e = blockIdx.z;
    const int cnt = g_cnt[e];
    const int m0 = blockIdx.y * 64;
    if (m0 >= cnt) return;
    const int off = g_off[e];
    const int n0 = blockIdx.x * 128;
    const float* __restrict__ Bm = Wd + (size_t)e * I_ * H_;
    const int N = H_, Kd = I_;

    __shared__ __align__(16) float As[2][16][68];
    __shared__ __align__(16) float Bs[2][16][132];
    const int tid = threadIdx.x;
    const int tx = tid & 15, ty = tid >> 4;
    const int arow = tid >> 2, akc = (tid & 3) * 4;
    const bool aok = (m0 + arow) < cnt;
    const float* Ap = g_rgu + (size_t)(off + (aok ? m0 + arow : 0)) * (2 * I_) + akc;

    unsigned long long acc[4][4];
    #pragma unroll
    for (int i = 0; i < 4; i++)
        #pragma unroll
        for (int j = 0; j < 4; j++) acc[i][j] = 0ull;

    {
        float4 v = make_float4(0.f, 0.f, 0.f, 0.f);
        if (aok) {
            float4 g = *(const float4*)Ap, u = *(const float4*)(Ap + I_);
            v = make_float4(silu1(g.x) * u.x, silu1(g.y) * u.y,
                            silu1(g.z) * u.z, silu1(g.w) * u.w);
        }
        As[0][akc + 0][arow] = v.x; As[0][akc + 1][arow] = v.y;
        As[0][akc + 2][arow] = v.z; As[0][akc + 3][arow] = v.w;
        #pragma unroll
        for (int l = 0; l < 2; l++) {
            int idx = tid + l * 256;
            int k = idx >> 5, nc = (idx & 31) * 4;
            *(float4*)&Bs[0][k][nc] = *(const float4*)(Bm + (size_t)k * N + n0 + nc);
        }
    }
    __syncthreads();

    const int nK = Kd >> 4;
    int buf = 0;
    for (int kt = 0; kt < nK; kt++) {
        float4 pa, pb[2];
        const bool nxt = (kt + 1) < nK;
        if (nxt) {
            int k0 = (kt + 1) << 4;
            pa = make_float4(0.f, 0.f, 0.f, 0.f);
            if (aok) {
                float4 g = *(const float4*)(Ap + k0), u = *(const float4*)(Ap + k0 + I_);
                pa = make_float4(silu1(g.x) * u.x, silu1(g.y) * u.y,
                                 silu1(g.z) * u.z, silu1(g.w) * u.w);
            }
            #pragma unroll
            for (int l = 0; l < 2; l++) {
                int idx = tid + l * 256;
                int k = idx >> 5, nc = (idx & 31) * 4;
                pb[l] = *(const float4*)(Bm + (size_t)(k0 + k) * N + n0 + nc);
            }
        }
        #pragma unroll
        for (int kk = 0; kk < 16; kk++) {
            float4 a0 = *(const float4*)&As[buf][kk][ty * 4];
            float4 b0 = *(const float4*)&Bs[buf][kk][tx * 4];
            float4 b1 = *(const float4*)&Bs[buf][kk][64 + tx * 4];
            unsigned long long bp0 = pk2(b0.x, b0.y), bp1 = pk2(b0.z, b0.w);
            unsigned long long bp2 = pk2(b1.x, b1.y), bp3 = pk2(b1.z, b1.w);
            float av[4] = {a0.x, a0.y, a0.z, a0.w};
            #pragma unroll
            for (int i = 0; i < 4; i++) {
                unsigned long long ad = pk2(av[i], av[i]);
                ffma2(acc[i][0], ad, bp0); ffma2(acc[i][1], ad, bp1);
                ffma2(acc[i][2], ad, bp2); ffma2(acc[i][3], ad, bp3);
            }
        }
        if (nxt) {
            int nb = buf ^ 1;
            As[nb][akc + 0][arow] = pa.x; As[nb][akc + 1][arow] = pa.y;
            As[nb][akc + 2][arow] = pa.z; As[nb][akc + 3][arow] = pa.w;
            #pragma unroll
            for (int l = 0; l < 2; l++) {
                int idx = tid + l * 256;
                int k = idx >> 5, nc = (idx & 31) * 4;
                *(float4*)&Bs[nb][k][nc] = pb[l];
            }
        }
        __syncthreads();
        buf ^= 1;
    }

    #pragma unroll
    for (int i = 0; i < 4; i++) {
        int row = m0 + ty * 4 + i;
        if (row < cnt) {
            int   slot = g_lslot[off + row];
            float w    = g_lw[off + row];
            float2 p0 = upk2(acc[i][0]), p1 = upk2(acc[i][1]);
            float2 p2 = upk2(acc[i][2]), p3 = upk2(acc[i][3]);
            float* c0 = g_rdwn + (size_t)slot * H_ + n0 + tx * 4;
            float* c1 = c0 + 64;
            *(float4*)c0 = make_float4(w * p0.x, w * p0.y, w * p1.x, w * p1.y);
            *(float4*)c1 = make_float4(w * p2.x, w * p2.y, w * p3.x, w * p3.y);
        }
    }
}

// ---------------- flash attention (unchanged, validated) --------------------
__global__ __launch_bounds__(256)
void flash_attn() {
    __shared__ float Qs[64][68];
    __shared__ float Ks[32][68];
    __shared__ float Vs[32][68];
    __shared__ float Ps[64][36];
    const int q0 = blockIdx.x * 64;
    const int h  = blockIdx.y;
    const int b  = blockIdx.z;
    const int tid = threadIdx.x;
    const size_t rs = 3 * H_;
    const float* qb = g_qkv + (size_t)b * S_ * rs + (size_t)h * HD_;
    const float* kb = qb + H_;
    const float* vb = qb + 2 * H_;
    const float scale = 0.125f;
    for (int i = tid; i < 64 * 64; i += 256) {
        int r = i >> 6, d = i & 63;
        Qs[r][d] = qb[(size_t)(q0 + r) * rs + d] * scale;
    }
    const int r  = tid >> 2;
    const int c4 = tid & 3;
    float m_i = -1e30f, l_i = 0.f;
    float acc[16];
    #pragma unroll
    for (int i = 0; i < 16; i++) acc[i] = 0.f;
    __syncthreads();
    for (int kt = 0; kt < S_; kt += 32) {
        for (int i = tid; i < 32 * 64; i += 256) {
            int rr = i >> 6, d = i & 63;
            Ks[rr][d] = kb[(size_t)(kt + rr) * rs + d];
            Vs[rr][d] = vb[(size_t)(kt + rr) * rs + d];
        }
        __syncthreads();
        float sc[8];
        float mx = -1e30f;
        const float4* qrow = (const float4*)&Qs[r][0];
        #pragma unroll
        for (int jj = 0; jj < 8; jj++) {
            int j = c4 * 8 + jj;
            const float4* krow = (const float4*)&Ks[j][0];
            float sv = 0.f;
            #pragma unroll
            for (int dv = 0; dv < 16; dv++) {
                float4 a = qrow[dv], bq = krow[dv];
                sv += a.x * bq.x + a.y * bq.y + a.z * bq.z + a.w * bq.w;
            }
            sc[jj] = sv; mx = fmaxf(mx, sv);
        }
        mx = fmaxf(mx, __shfl_xor_sync(0xffffffffu, mx, 1));
        mx = fmaxf(mx, __shfl_xor_sync(0xffffffffu, mx, 2));
        float m_new = fmaxf(m_i, mx);
        float alpha = expf(m_i - m_new);
        float psum = 0.f;
        #pragma unroll
        for (int jj = 0; jj < 8; jj++) {
            float p = expf(sc[jj] - m_new);
            Ps[r][c4 * 8 + jj] = p;
            psum += p;
        }
        psum += __shfl_xor_sync(0xffffffffu, psum, 1);
        psum += __shfl_xor_sync(0xffffffffu, psum, 2);
        l_i = l_i * alpha + psum;
        m_i = m_new;
        #pragma unroll
        for (int i = 0; i < 16; i++) acc[i] *= alpha;
        __syncwarp();
        #pragma unroll
        for (int i = 0; i < 16; i++) {
            int d = c4 * 16 + i;
            float s = 0.f;
            #pragma unroll 8
            for (int j = 0; j < 32; j++) s += Ps[r][j] * Vs[j][d];
            acc[i] += s;
        }
        __syncthreads();
    }
    float inv = 1.f / l_i;
    float* ob = g_attn + (size_t)((b * S_ + q0 + r)) * H_ + (size_t)h * HD_;
    #pragma unroll
    for (int i = 0; i < 16; i++) ob[c4 * 16 + i] = acc[i] * inv;
}

// ---------------- residual + rmsnorm ---------------------------------------
__global__ __launch_bounds__(256)
void resid_rms(const float* __restrict__ a, const float* __restrict__ b,
               float* __restrict__ o) {
    const int t = blockIdx.x;
    float v[4]; float ss = 0.f;
    #pragma unroll
    for (int i = 0; i < 4; i++) {
        int j = i * 256 + threadIdx.x;
        float s = a[(size_t)t * H_ + j] + b[(size_t)t * H_ + j];
        v[i] = s; ss += s * s;
    }
    ss = block_sum256(ss);
    float inv = rsqrtf(ss * (1.f / H_) + EPS_);
    #pragma unroll
    for (int i = 0; i < 4; i++) {
        int j = i * 256 + threadIdx.x;
        o[(size_t)t * H_ + j] = v[i] * inv;
    }
}

// ---------------- routing ---------------------------------------------------
__global__ void zero_small() {
    int i = threadIdx.x;
    if (i < E_) { g_Pi[i] = 0.f; g_cnt[i] = 0; }
    if (i < D_)   g_comm[i] = 0.f;
}

__global__ void routing_kernel(const float* __restrict__ Wr) {
    const int t = blockIdx.x;
    const int e = threadIdx.x;   // 32 threads
    const float* xr = g_h1 + (size_t)t * H_;
    float logit = 0.f;
    for (int j = 0; j < H_; j++) logit += xr[j] * Wr[(size_t)j * E_ + e];
    float m = logit;
    #pragma unroll
    for (int o = 16; o; o >>= 1) m = fmaxf(m, __shfl_xor_sync(0xffffffffu, m, o));
    float ex = expf(logit - m);
    float s = ex;
    #pragma unroll
    for (int o = 16; o; o >>= 1) s += __shfl_xor_sync(0xffffffffu, s, o);
    float prob = ex / s;
    atomicAdd(&g_Pi[e], prob);
    __shared__ float sp[E_];
    sp[e] = prob;
    __syncwarp();
    if (e == 0) {
        float ds[D_];
        #pragma unroll
        for (int d = 0; d < D_; d++)
            ds[d] = sp[4 * d] + sp[4 * d + 1] + sp[4 * d + 2] + sp[4 * d + 3];
        bool dsel[D_] = {};
        for (int rsel = 0; rsel < KD_; rsel++) {
            int best = -1; float bv = -1e30f;
            for (int d = 0; d < D_; d++)
                if (!dsel[d] && ds[d] > bv) { bv = ds[d]; best = d; }
            dsel[best] = true;
        }
        float masked[E_];
        #pragma unroll
        for (int i = 0; i < E_; i++)
            masked[i] = dsel[i >> 2] ? sp[i] : -1e30f;
        int   iv[K_]; float wv[K_];
        for (int rsel = 0; rsel < K_; rsel++) {
            int best = 0; float bv = -1e31f;
            for (int i = 0; i < E_; i++)
                if (masked[i] > bv) { bv = masked[i]; best = i; }
            iv[rsel] = best; wv[rsel] = bv;
            masked[best] = -1e31f;
        }
        float mm = wv[0];
        float ssum = 0.f;
        #pragma unroll
        for (int rsel = 0; rsel < K_; rsel++) { wv[rsel] = expf(wv[rsel] - mm); ssum += wv[rsel]; }
        bool hit[D_] = {};
        #pragma unroll
        for (int rsel = 0; rsel < K_; rsel++) hit[iv[rsel] >> 2] = true;
        for (int d = 0; d < D_; d++)
            if (hit[d]) atomicAdd(&g_comm[d], 1.0f);
        #pragma unroll
        for (int rsel = 0; rsel < K_; rsel++) {
            int idx = t * K_ + rsel;
            g_sel_e[idx] = iv[rsel];
            g_sel_w[idx] = wv[rsel] / ssum;
            atomicAdd(&g_cnt[iv[rsel]], 1);
        }
    }
}

__global__ void offsets_kernel() {
    if (threadIdx.x == 0) {
        int s = 0;
        for (int e = 0; e < E_; e++) { g_off[e] = s; g_cur[e] = s; s += g_cnt[e]; }
    }
}

__global__ void scatter_kernel() {
    int i = blockIdx.x * 256 + threadIdx.x;
    if (i >= TK_) return;
    int e = g_sel_e[i];
    int pos = atomicAdd(&g_cur[e], 1);
    g_ltok[pos]  = i / K_;
    g_lslot[pos] = i;
    g_lw[pos]    = g_sel_w[i];
}

// ---------------- final combine + rmsnorm + aux ------------------------------
__global__ __launch_bounds__(256)
void final_kernel(float* __restrict__ out) {
    const int t = blockIdx.x;
    float v[4]; float ss = 0.f;
    #pragma unroll
    for (int i = 0; i < 4; i++) {
        int j = i * 256 + threadIdx.x;
        float s = g_h1[(size_t)t * H_ + j] + g_sout[(size_t)t * H_ + j];
        #pragma unroll
        for (int k = 0; k < K_; k++)
            s += g_rdwn[(size_t)(t * K_ + k) * H_ + j];
        v[i] = s; ss += s * s;
    }
    ss = block_sum256(ss);
    float inv = rsqrtf(ss * (1.f / H_) + EPS_);
    #pragma unroll
    for (int i = 0; i < 4; i++) {
        int j = i * 256 + threadIdx.x;
        out[(size_t)t * H_ + j] = v[i] * inv;
    }
}

__global__ void aux_kernel(float* out, int out_size) {
    if (out_size <= T_ * H_) return;
    const float fTK = (float)TK_ + 1e-10f;
    float fi[E_], Pi[E_];
    float s1 = 0.f;
    for (int e = 0; e < E_; e++) {
        fi[e] = (float)g_cnt[e] / fTK;
        Pi[e] = g_Pi[e] / (float)T_;
        s1 += fi[e] * Pi[e];
    }
    float eb = fminf(s1 * 0.003f, 10.f);
    float dP[D_];
    float s2 = 0.f;
    for (int d = 0; d < D_; d++) {
        float df = (fi[4*d] + fi[4*d+1] + fi[4*d+2] + fi[4*d+3]) * 0.25f;
        dP[d]    = Pi[4*d] + Pi[4*d+1] + Pi[4*d+2] + Pi[4*d+3];
        s2 += df * dP[d];
    }
    float db = fminf(s2 * 0.05f, 10.f);
    float s3 = 0.f;
    for (int d = 0; d < D_; d++) {
        float fc = g_comm[d] / ((float)(T_ * KD_) + 1e-10f);
        s3 += fc * dP[d];
    }
    float cb = fminf(s3 * 0.02f, 10.f);
    out[T_ * H_] = eb + db + cb;
}

// ---------------- host driver ------------------------------------------------
extern "C" void kernel_launch(void* const* d_in, const int* in_sizes, int n_in,
                              void* d_out, int out_size) {
    const float* x     = (const float*)d_in[0];
    const float* Wqkv  = (const float*)d_in[1];
    const float* Wo    = (const float*)d_in[2];
    const float* Wgu_s = (const float*)d_in[3];
    const float* Wd_s  = (const float*)d_in[4];
    const float* Wr    = (const float*)d_in[5];
    const float* Wgu   = (const float*)d_in[6];
    const float* Wd    = (const float*)d_in[7];
    float* out = (float*)d_out;

    float *p_qkv, *p_attn, *p_tmp, *p_h1, *p_sgu;
    cudaGetSymbolAddress((void**)&p_qkv,  g_qkv);
    cudaGetSymbolAddress((void**)&p_attn, g_attn);
    cudaGetSymbolAddress((void**)&p_tmp,  g_tmp);
    cudaGetSymbolAddress((void**)&p_h1,   g_h1);
    cudaGetSymbolAddress((void**)&p_sgu,  g_sgu);

    zero_small<<<1, 64>>>();

    // qkv = x @ Wqkv  (1024 x 1024 x 3072)
    sgemm_nn128<<<dim3(3 * H_ / 128, T_ / 128), 256>>>(x, Wqkv, p_qkv, H_, 3 * H_, 0);

    // attention
    flash_attn<<<dim3(S_ / 64, NH_, B_), 256>>>();

    // proj = attn @ Wo, h1 = rmsnorm(x + proj)
    sgemm_nn128<<<dim3(H_ / 128, T_ / 128), 256>>>(p_attn, Wo, p_tmp, H_, H_, 0);
    resid_rms<<<T_, 256>>>(x, p_tmp, p_h1);

    // shared experts (2): up GEMM, then down GEMM with fused SwiGLU
    for (int e = 0; e < 2; e++) {
        sgemm_nn128<<<dim3(2 * I_ / 128, T_ / 128), 256>>>(
            p_h1, Wgu_s + (size_t)e * H_ * 2 * I_, p_sgu, H_, 2 * I_, 0);
        sgemm_shared_down<<<dim3(H_ / 128, T_ / 128), 256>>>(
            Wd_s + (size_t)e * I_ * H_, e);
    }

    // routing + sparse dispatch
    routing_kernel<<<T_, 32>>>(Wr);
    offsets_kernel<<<1, 32>>>();
    scatter_kernel<<<(TK_ + 255) / 256, 256>>>();

    // routed up-proj (gathered) and down-proj (fused SwiGLU, weighted scatter)
    sgemm_up_r64<<<dim3(2 * I_ / 128, T_ / 64, E_), 256>>>(Wgu);
    sgemm_down_r64<<<dim3(H_ / 128, T_ / 64, E_), 256>>>(Wd);

    // final residual + rmsnorm + aux
    final_kernel<<<T_, 256>>>(out);
    aux_kernel<<<1, 1>>>(out, out_size);
}

// round 5
// speedup vs baseline: 1.7581x; 1.6274x over previous
#include <cuda_runtime.h>
#include <cuda_bf16.h>
#include <math.h>
#include <stdint.h>

// ---------------- problem constants ----------------
#define B_   2
#define S_   512
#define T_   1024          // B*S tokens
#define H_   1024
#define NH_  16
#define HD_  64
#define E_   32
#define D_   8
#define K_   6
#define KD_  3
#define I_   1536
#define EPS_ 1e-5f
#define TK_  (T_*K_)       // 6144 assignments

// ---------------- device scratch (static, allowed) ----------------
__device__ float g_qkv [T_*3*H_];
__device__ float g_attn[T_*H_];
__device__ float g_tmp [T_*H_];
__device__ float g_h1  [T_*H_];
__device__ float g_sgu [T_*2*I_];     // shared-expert gate/up (fp32)
__device__ float g_sout[T_*H_];
__device__ float g_rgu [TK_*2*I_];    // routed gate/up (fp32)
__device__ float g_rdwn[TK_*H_];      // per-slot routed output

__device__ float g_Pi  [E_];
__device__ float g_comm[D_];
__device__ int   g_cnt [E_];
__device__ int   g_off [E_];
__device__ int   g_cur [E_];
__device__ int   g_sel_e[TK_];
__device__ float g_sel_w[TK_];
__device__ int   g_ltok [TK_];
__device__ int   g_lslot[TK_];
__device__ float g_lw   [TK_];

// ---------------- helpers ----------------
__device__ __forceinline__ float silu1(float g) { return g / (1.f + expf(-g)); }

__device__ __forceinline__ float block_sum256(float v) {
    __shared__ float red[8];
    __shared__ float tot;
    #pragma unroll
    for (int o = 16; o; o >>= 1) v += __shfl_xor_sync(0xffffffffu, v, o);
    if ((threadIdx.x & 31) == 0) red[threadIdx.x >> 5] = v;
    __syncthreads();
    if (threadIdx.x < 8) {
        float s = red[threadIdx.x];
        #pragma unroll
        for (int o = 4; o; o >>= 1) s += __shfl_xor_sync(0xffu, s, o);
        if (threadIdx.x == 0) tot = s;
    }
    __syncthreads();
    return tot;
}

// ---------------- mma/ldmatrix primitives -----------------------------------
__device__ __forceinline__ uint32_t smem_u32(const void* p) {
    return (uint32_t)__cvta_generic_to_shared(p);
}
__device__ __forceinline__ void ldm_x4(uint32_t r[4], uint32_t addr) {
    asm volatile("ldmatrix.sync.aligned.m8n8.x4.shared.b16 {%0,%1,%2,%3},[%4];"
        : "=r"(r[0]), "=r"(r[1]), "=r"(r[2]), "=r"(r[3]) : "r"(addr));
}
__device__ __forceinline__ void ldm_x4t(uint32_t r[4], uint32_t addr) {
    asm volatile("ldmatrix.sync.aligned.m8n8.x4.trans.shared.b16 {%0,%1,%2,%3},[%4];"
        : "=r"(r[0]), "=r"(r[1]), "=r"(r[2]), "=r"(r[3]) : "r"(addr));
}
__device__ __forceinline__ void mma_bf16(float c[4], const uint32_t a[4],
                                         uint32_t b0, uint32_t b1) {
    asm volatile(
        "mma.sync.aligned.m16n8k16.row.col.f32.bf16.bf16.f32 "
        "{%0,%1,%2,%3},{%4,%5,%6,%7},{%8,%9},{%0,%1,%2,%3};"
        : "+f"(c[0]), "+f"(c[1]), "+f"(c[2]), "+f"(c[3])
        : "r"(a[0]), "r"(a[1]), "r"(a[2]), "r"(a[3]), "r"(b0), "r"(b1));
}

// split fp32 pair into bf16 hi + lo pair
__device__ __forceinline__ void split2(float2 v, __nv_bfloat162& h, __nv_bfloat162& l) {
    h = __float22bfloat162_rn(v);
    float2 r = make_float2(v.x - __bfloat162float(h.x), v.y - __bfloat162float(h.y));
    l = __float22bfloat162_rn(r);
}
// stage 8 floats -> 8 hi halfs + 8 lo halfs (16B stores)
__device__ __forceinline__ void stage8(__nv_bfloat16* dh, __nv_bfloat16* dl,
                                       float4 f0, float4 f1) {
    __nv_bfloat162 h[4], l[4];
    split2(make_float2(f0.x, f0.y), h[0], l[0]);
    split2(make_float2(f0.z, f0.w), h[1], l[1]);
    split2(make_float2(f1.x, f1.y), h[2], l[2]);
    split2(make_float2(f1.z, f1.w), h[3], l[3]);
    *(uint4*)dh = *(uint4*)h;
    *(uint4*)dl = *(uint4*)l;
}
// stage 4 floats -> 4 hi + 4 lo halfs (8B stores)
__device__ __forceinline__ void stage4(__nv_bfloat16* dh, __nv_bfloat16* dl, float4 f0) {
    __nv_bfloat162 h[2], l[2];
    split2(make_float2(f0.x, f0.y), h[0], l[0]);
    split2(make_float2(f0.z, f0.w), h[1], l[1]);
    *(uint2*)dh = *(uint2*)h;
    *(uint2*)dl = *(uint2*)l;
}

// A-smem pitch 24 halfs (48B), B-smem pitch 136 halfs (272B): ldmatrix conflict-free
#define AP_ 24
#define BP_ 136

// One k16 step of the 3-term split GEMM for one warp.
// acc layout: acc[mf*NF + nf][4], warp tile = 32 x (NF*8).
template<int NF>
__device__ __forceinline__ void compute_step(
    const __nv_bfloat16* Ah, const __nv_bfloat16* Al,
    const __nv_bfloat16* Bh, const __nv_bfloat16* Bl,
    int wm, int wn, int lane, float (*acc)[4])
{
    uint32_t ah[2][4], al[2][4];
    const int arow = lane & 15, acol = (lane >> 4) * 8;
    #pragma unroll
    for (int mf = 0; mf < 2; mf++) {
        int off = (wm * 32 + mf * 16 + arow) * AP_ + acol;
        ldm_x4(ah[mf], smem_u32(Ah + off));
        ldm_x4(al[mf], smem_u32(Al + off));
    }
    const int bkr = lane & 15;
    const int bnl = (lane >> 4) * 8;
    #pragma unroll
    for (int nf2 = 0; nf2 < NF / 2; nf2++) {
        int off = bkr * BP_ + wn * (NF * 8) + nf2 * 16 + bnl;
        uint32_t bh[4], bl4[4];
        ldm_x4t(bh,  smem_u32(Bh + off));
        ldm_x4t(bl4, smem_u32(Bl + off));
        #pragma unroll
        for (int mf = 0; mf < 2; mf++) {
            float* c0 = acc[mf * NF + nf2 * 2 + 0];
            float* c1 = acc[mf * NF + nf2 * 2 + 1];
            mma_bf16(c0, ah[mf], bh[0],  bh[1]);
            mma_bf16(c0, ah[mf], bl4[0], bl4[1]);
            mma_bf16(c0, al[mf], bh[0],  bh[1]);
            mma_bf16(c1, ah[mf], bh[2],  bh[3]);
            mma_bf16(c1, ah[mf], bl4[2], bl4[3]);
            mma_bf16(c1, al[mf], bh[2],  bh[3]);
        }
    }
}

// ============================================================================
// Dense GEMM: C[M,N] = A[M,Kd] @ B[Kd,N], fp32 in/out, bf16-split tensor core.
// BM=128, BN=128, BK=16. grid=(N/128, M/128), block=256 (8 warps: 4m x 2n).
// ============================================================================
__global__ __launch_bounds__(256)
void mma_dense(const float* __restrict__ A, const float* __restrict__ Bw,
               float* __restrict__ C, int Kd, int N, int accum)
{
    constexpr int NF = 8;
    __shared__ __align__(16) __nv_bfloat16 sAh[2][128][AP_];
    __shared__ __align__(16) __nv_bfloat16 sAl[2][128][AP_];
    __shared__ __align__(16) __nv_bfloat16 sBh[2][16][BP_];
    __shared__ __align__(16) __nv_bfloat16 sBl[2][16][BP_];
    const int tid = threadIdx.x, lane = tid & 31, wid = tid >> 5;
    const int wm = wid & 3, wn = wid >> 2;
    const int m0 = blockIdx.y * 128, n0 = blockIdx.x * 128;

    const int ar = tid >> 1, akc = (tid & 1) * 8;
    const int bk = tid >> 4, bnc = (tid & 15) * 8;
    const float* Ag = A + (size_t)(m0 + ar) * Kd + akc;
    const float* Bg = Bw + (size_t)bk * N + n0 + bnc;

    float acc[2 * NF][4];
    #pragma unroll
    for (int i = 0; i < 2 * NF; i++)
        #pragma unroll
        for (int j = 0; j < 4; j++) acc[i][j] = 0.f;

    float4 fa0 = *(const float4*)Ag, fa1 = *(const float4*)(Ag + 4);
    float4 fb0 = *(const float4*)Bg, fb1 = *(const float4*)(Bg + 4);
    stage8(&sAh[0][ar][akc], &sAl[0][ar][akc], fa0, fa1);
    stage8(&sBh[0][bk][bnc], &sBl[0][bk][bnc], fb0, fb1);
    __syncthreads();

    const int nK = Kd >> 4;
    int buf = 0;
    for (int kt = 0; kt < nK; kt++) {
        const bool nxt = (kt + 1) < nK;
        if (nxt) {
            int k0 = (kt + 1) << 4;
            fa0 = *(const float4*)(Ag + k0); fa1 = *(const float4*)(Ag + k0 + 4);
            fb0 = *(const float4*)(Bg + (size_t)k0 * N);
            fb1 = *(const float4*)(Bg + (size_t)k0 * N + 4);
        }
        compute_step<NF>(&sAh[buf][0][0], &sAl[buf][0][0],
                         &sBh[buf][0][0], &sBl[buf][0][0], wm, wn, lane, acc);
        if (nxt) {
            int nb = buf ^ 1;
            stage8(&sAh[nb][ar][akc], &sAl[nb][ar][akc], fa0, fa1);
            stage8(&sBh[nb][bk][bnc], &sBl[nb][bk][bnc], fb0, fb1);
        }
        __syncthreads();
        buf ^= 1;
    }

    #pragma unroll
    for (int mf = 0; mf < 2; mf++)
        #pragma unroll
        for (int nf = 0; nf < NF; nf++) {
            float* c = acc[mf * NF + nf];
            int r0  = m0 + wm * 32 + mf * 16 + (lane >> 2);
            int col = n0 + wn * (NF * 8) + nf * 8 + (lane & 3) * 2;
            float* p0 = C + (size_t)r0 * N + col;
            float* p1 = C + (size_t)(r0 + 8) * N + col;
            if (accum) {
                p0[0] += c[0]; p0[1] += c[1]; p1[0] += c[2]; p1[1] += c[3];
            } else {
                p0[0] = c[0]; p0[1] = c[1]; p1[0] = c[2]; p1[1] = c[3];
            }
        }
}

// ============================================================================
// Shared-expert down GEMM: A = silu(g)*u from g_sgu (fused), C = g_sout.
// M=T_, N=H_, Kd=I_. Same tiling as mma_dense.
// ============================================================================
__global__ __launch_bounds__(256)
void mma_shared_down(const float* __restrict__ Wd_s, int accum)
{
    constexpr int NF = 8;
    const int N = H_, Kd = I_;
    __shared__ __align__(16) __nv_bfloat16 sAh[2][128][AP_];
    __shared__ __align__(16) __nv_bfloat16 sAl[2][128][AP_];
    __shared__ __align__(16) __nv_bfloat16 sBh[2][16][BP_];
    __shared__ __align__(16) __nv_bfloat16 sBl[2][16][BP_];
    const int tid = threadIdx.x, lane = tid & 31, wid = tid >> 5;
    const int wm = wid & 3, wn = wid >> 2;
    const int m0 = blockIdx.y * 128, n0 = blockIdx.x * 128;

    const int ar = tid >> 1, akc = (tid & 1) * 8;
    const int bk = tid >> 4, bnc = (tid & 15) * 8;
    const float* Gg = g_sgu + (size_t)(m0 + ar) * (2 * I_) + akc;
    const float* Bg = Wd_s + (size_t)bk * N + n0 + bnc;

    float acc[2 * NF][4];
    #pragma unroll
    for (int i = 0; i < 2 * NF; i++)
        #pragma unroll
        for (int j = 0; j < 4; j++) acc[i][j] = 0.f;

    float4 fa0, fa1, fb0, fb1;
    {
        float4 gg0 = *(const float4*)Gg,        gg1 = *(const float4*)(Gg + 4);
        float4 uu0 = *(const float4*)(Gg + I_), uu1 = *(const float4*)(Gg + I_ + 4);
        fa0 = make_float4(silu1(gg0.x)*uu0.x, silu1(gg0.y)*uu0.y,
                          silu1(gg0.z)*uu0.z, silu1(gg0.w)*uu0.w);
        fa1 = make_float4(silu1(gg1.x)*uu1.x, silu1(gg1.y)*uu1.y,
                          silu1(gg1.z)*uu1.z, silu1(gg1.w)*uu1.w);
        fb0 = *(const float4*)Bg; fb1 = *(const float4*)(Bg + 4);
    }
    stage8(&sAh[0][ar][akc], &sAl[0][ar][akc], fa0, fa1);
    stage8(&sBh[0][bk][bnc], &sBl[0][bk][bnc], fb0, fb1);
    __syncthreads();

    const int nK = Kd >> 4;
    int buf = 0;
    for (int kt = 0; kt < nK; kt++) {
        const bool nxt = (kt + 1) < nK;
        if (nxt) {
            int k0 = (kt + 1) << 4;
            float4 gg0 = *(const float4*)(Gg + k0), gg1 = *(const float4*)(Gg + k0 + 4);
            float4 uu0 = *(const float4*)(Gg + k0 + I_), uu1 = *(const float4*)(Gg + k0 + I_ + 4);
            fa0 = make_float4(silu1(gg0.x)*uu0.x, silu1(gg0.y)*uu0.y,
                              silu1(gg0.z)*uu0.z, silu1(gg0.w)*uu0.w);
            fa1 = make_float4(silu1(gg1.x)*uu1.x, silu1(gg1.y)*uu1.y,
                              silu1(gg1.z)*uu1.z, silu1(gg1.w)*uu1.w);
            fb0 = *(const float4*)(Bg + (size_t)k0 * N);
            fb1 = *(const float4*)(Bg + (size_t)k0 * N + 4);
        }
        compute_step<NF>(&sAh[buf][0][0], &sAl[buf][0][0],
                         &sBh[buf][0][0], &sBl[buf][0][0], wm, wn, lane, acc);
        if (nxt) {
            int nb = buf ^ 1;
            stage8(&sAh[nb][ar][akc], &sAl[nb][ar][akc], fa0, fa1);
            stage8(&sBh[nb][bk][bnc], &sBl[nb][bk][bnc], fb0, fb1);
        }
        __syncthreads();
        buf ^= 1;
    }

    #pragma unroll
    for (int mf = 0; mf < 2; mf++)
        #pragma unroll
        for (int nf = 0; nf < NF; nf++) {
            float* c = acc[mf * NF + nf];
            int r0  = m0 + wm * 32 + mf * 16 + (lane >> 2);
            int col = n0 + wn * (NF * 8) + nf * 8 + (lane & 3) * 2;
            float* p0 = g_sout + (size_t)r0 * N + col;
            float* p1 = g_sout + (size_t)(r0 + 8) * N + col;
            if (accum) {
                p0[0] += c[0]; p0[1] += c[1]; p1[0] += c[2]; p1[1] += c[3];
            } else {
                p0[0] = c[0]; p0[1] = c[1]; p1[0] = c[2]; p1[1] = c[3];
            }
        }
}

// ============================================================================
// Routed up GEMM: BM=64 (8 warps: 2m x 4n, NF=4), gathered A rows from g_h1.
// grid=(2I/128, T/64, E).
// ============================================================================
__global__ __launch_bounds__(256)
void mma_up_routed(const float* __restrict__ Wgu)
{
    constexpr int NF = 4;
    const int e = blockIdx.z;
    const int cnt = g_cnt[e];
    const int m0 = blockIdx.y * 64;
    if (m0 >= cnt) return;
    const int off = g_off[e];
    const int n0 = blockIdx.x * 128;
    const int N = 2 * I_, Kd = H_;
    const float* __restrict__ Bw = Wgu + (size_t)e * H_ * 2 * I_;

    __shared__ __align__(16) __nv_bfloat16 sAh[2][64][AP_];
    __shared__ __align__(16) __nv_bfloat16 sAl[2][64][AP_];
    __shared__ __align__(16) __nv_bfloat16 sBh[2][16][BP_];
    __shared__ __align__(16) __nv_bfloat16 sBl[2][16][BP_];
    const int tid = threadIdx.x, lane = tid & 31, wid = tid >> 5;
    const int wm = wid & 1, wn = wid >> 1;
    const int ar = tid >> 2, akc = (tid & 3) * 4;
    const int bk = tid >> 4, bnc = (tid & 15) * 8;

    const int tok = (m0 + ar < cnt) ? g_ltok[off + m0 + ar] : -1;
    const float* Ag = (tok >= 0) ? (g_h1 + (size_t)tok * H_ + akc) : g_h1;
    const float* Bg = Bw + (size_t)bk * N + n0 + bnc;

    float acc[2 * NF][4];
    #pragma unroll
    for (int i = 0; i < 2 * NF; i++)
        #pragma unroll
        for (int j = 0; j < 4; j++) acc[i][j] = 0.f;

    float4 fa = (tok >= 0) ? *(const float4*)Ag : make_float4(0.f,0.f,0.f,0.f);
    float4 fb0 = *(const float4*)Bg, fb1 = *(const float4*)(Bg + 4);
    stage4(&sAh[0][ar][akc], &sAl[0][ar][akc], fa);
    stage8(&sBh[0][bk][bnc], &sBl[0][bk][bnc], fb0, fb1);
    __syncthreads();

    const int nK = Kd >> 4;
    int buf = 0;
    for (int kt = 0; kt < nK; kt++) {
        const bool nxt = (kt + 1) < nK;
        if (nxt) {
            int k0 = (kt + 1) << 4;
            fa = (tok >= 0) ? *(const float4*)(Ag + k0) : make_float4(0.f,0.f,0.f,0.f);
            fb0 = *(const float4*)(Bg + (size_t)k0 * N);
            fb1 = *(const float4*)(Bg + (size_t)k0 * N + 4);
        }
        compute_step<NF>(&sAh[buf][0][0], &sAl[buf][0][0],
                         &sBh[buf][0][0], &sBl[buf][0][0], wm, wn, lane, acc);
        if (nxt) {
            int nb = buf ^ 1;
            stage4(&sAh[nb][ar][akc], &sAl[nb][ar][akc], fa);
            stage8(&sBh[nb][bk][bnc], &sBl[nb][bk][bnc], fb0, fb1);
        }
        __syncthreads();
        buf ^= 1;
    }

    #pragma unroll
    for (int mf = 0; mf < 2; mf++)
        #pragma unroll
        for (int nf = 0; nf < NF; nf++) {
            float* c = acc[mf * NF + nf];
            int lr0 = m0 + wm * 32 + mf * 16 + (lane >> 2);
            int col = n0 + wn * (NF * 8) + nf * 8 + (lane & 3) * 2;
            if (lr0 < cnt) {
                float* p = g_rgu + (size_t)(off + lr0) * N + col;
                p[0] = c[0]; p[1] = c[1];
            }
            if (lr0 + 8 < cnt) {
                float* p = g_rgu + (size_t)(off + lr0 + 8) * N + col;
                p[0] = c[2]; p[1] = c[3];
            }
        }
}

// ============================================================================
// Routed down GEMM: BM=64, fused SwiGLU A from g_rgu, weighted scatter out.
// grid=(H/128, T/64, E).
// ============================================================================
__global__ __launch_bounds__(256)
void mma_down_routed(const float* __restrict__ Wd)
{
    constexpr int NF = 4;
    const int e = blockIdx.z;
    const int cnt = g_cnt[e];
    const int m0 = blockIdx.y * 64;
    if (m0 >= cnt) return;
    const int off = g_off[e];
    const int n0 = blockIdx.x * 128;
    const int N = H_, Kd = I_;
    const float* __restrict__ Bw = Wd + (size_t)e * I_ * H_;

    __shared__ __align__(16) __nv_bfloat16 sAh[2][64][AP_];
    __shared__ __align__(16) __nv_bfloat16 sAl[2][64][AP_];
    __shared__ __align__(16) __nv_bfloat16 sBh[2][16][BP_];
    __shared__ __align__(16) __nv_bfloat16 sBl[2][16][BP_];
    const int tid = threadIdx.x, lane = tid & 31, wid = tid >> 5;
    const int wm = wid & 1, wn = wid >> 1;
    const int ar = tid >> 2, akc = (tid & 3) * 4;
    const int bk = tid >> 4, bnc = (tid & 15) * 8;

    const bool aok = (m0 + ar) < cnt;
    const float* Ag = g_rgu + (size_t)(off + (aok ? m0 + ar : 0)) * (2 * I_) + akc;
    const float* Bg = Bw + (size_t)bk * N + n0 + bnc;

    float acc[2 * NF][4];
    #pragma unroll
    for (int i = 0; i < 2 * NF; i++)
        #pragma unroll
        for (int j = 0; j < 4; j++) acc[i][j] = 0.f;

    float4 fa = make_float4(0.f,0.f,0.f,0.f);
    if (aok) {
        float4 gg = *(const float4*)Ag, uu = *(const float4*)(Ag + I_);
        fa = make_float4(silu1(gg.x)*uu.x, silu1(gg.y)*uu.y,
                         silu1(gg.z)*uu.z, silu1(gg.w)*uu.w);
    }
    float4 fb0 = *(const float4*)Bg, fb1 = *(const float4*)(Bg + 4);
    stage4(&sAh[0][ar][akc], &sAl[0][ar][akc], fa);
    stage8(&sBh[0][bk][bnc], &sBl[0][bk][bnc], fb0, fb1);
    __syncthreads();

    const int nK = Kd >> 4;
    int buf = 0;
    for (int kt = 0; kt < nK; kt++) {
        const bool nxt = (kt + 1) < nK;
        if (nxt) {
            int k0 = (kt + 1) << 4;
            fa = make_float4(0.f,0.f,0.f,0.f);
            if (aok) {
                float4 gg = *(const float4*)(Ag + k0), uu = *(const float4*)(Ag + k0 + I_);
                fa = make_float4(silu1(gg.x)*uu.x, silu1(gg.y)*uu.y,
                                 silu1(gg.z)*uu.z, silu1(gg.w)*uu.w);
            }
            fb0 = *(const float4*)(Bg + (size_t)k0 * N);
            fb1 = *(const float4*)(Bg + (size_t)k0 * N + 4);
        }
        compute_step<NF>(&sAh[buf][0][0], &sAl[buf][0][0],
                         &sBh[buf][0][0], &sBl[buf][0][0], wm, wn, lane, acc);
        if (nxt) {
            int nb = buf ^ 1;
            stage4(&sAh[nb][ar][akc], &sAl[nb][ar][akc], fa);
            stage8(&sBh[nb][bk][bnc], &sBl[nb][bk][bnc], fb0, fb1);
        }
        __syncthreads();
        buf ^= 1;
    }

    #pragma unroll
    for (int mf = 0; mf < 2; mf++)
        #pragma unroll
        for (int nf = 0; nf < NF; nf++) {
            float* c = acc[mf * NF + nf];
            int lr0 = m0 + wm * 32 + mf * 16 + (lane >> 2);
            int col = n0 + wn * (NF * 8) + nf * 8 + (lane & 3) * 2;
            if (lr0 < cnt) {
                int slot = g_lslot[off + lr0];
                float w  = g_lw[off + lr0];
                float* p = g_rdwn + (size_t)slot * H_ + col;
                p[0] = w * c[0]; p[1] = w * c[1];
            }
            if (lr0 + 8 < cnt) {
                int slot = g_lslot[off + lr0 + 8];
                float w  = g_lw[off + lr0 + 8];
                float* p = g_rdwn + (size_t)slot * H_ + col;
                p[0] = w * c[2]; p[1] = w * c[3];
            }
        }
}

// ---------------- flash attention (fp32, validated) --------------------------
__global__ __launch_bounds__(256)
void flash_attn() {
    __shared__ float Qs[64][68];
    __shared__ float Ks[32][68];
    __shared__ float Vs[32][68];
    __shared__ float Ps[64][36];
    const int q0 = blockIdx.x * 64;
    const int h  = blockIdx.y;
    const int b  = blockIdx.z;
    const int tid = threadIdx.x;
    const size_t rs = 3 * H_;
    const float* qb = g_qkv + (size_t)b * S_ * rs + (size_t)h * HD_;
    const float* kb = qb + H_;
    const float* vb = qb + 2 * H_;
    const float scale = 0.125f;
    for (int i = tid; i < 64 * 64; i += 256) {
        int r = i >> 6, d = i & 63;
        Qs[r][d] = qb[(size_t)(q0 + r) * rs + d] * scale;
    }
    const int r  = tid >> 2;
    const int c4 = tid & 3;
    float m_i = -1e30f, l_i = 0.f;
    float acc[16];
    #pragma unroll
    for (int i = 0; i < 16; i++) acc[i] = 0.f;
    __syncthreads();
    for (int kt = 0; kt < S_; kt += 32) {
        for (int i = tid; i < 32 * 64; i += 256) {
            int rr = i >> 6, d = i & 63;
            Ks[rr][d] = kb[(size_t)(kt + rr) * rs + d];
            Vs[rr][d] = vb[(size_t)(kt + rr) * rs + d];
        }
        __syncthreads();
        float sc[8];
        float mx = -1e30f;
        const float4* qrow = (const float4*)&Qs[r][0];
        #pragma unroll
        for (int jj = 0; jj < 8; jj++) {
            int j = c4 * 8 + jj;
            const float4* krow = (const float4*)&Ks[j][0];
            float sv = 0.f;
            #pragma unroll
            for (int dv = 0; dv < 16; dv++) {
                float4 a = qrow[dv], bq = krow[dv];
                sv += a.x * bq.x + a.y * bq.y + a.z * bq.z + a.w * bq.w;
            }
            sc[jj] = sv; mx = fmaxf(mx, sv);
        }
        mx = fmaxf(mx, __shfl_xor_sync(0xffffffffu, mx, 1));
        mx = fmaxf(mx, __shfl_xor_sync(0xffffffffu, mx, 2));
        float m_new = fmaxf(m_i, mx);
        float alpha = expf(m_i - m_new);
        float psum = 0.f;
        #pragma unroll
        for (int jj = 0; jj < 8; jj++) {
            float p = expf(sc[jj] - m_new);
            Ps[r][c4 * 8 + jj] = p;
            psum += p;
        }
        psum += __shfl_xor_sync(0xffffffffu, psum, 1);
        psum += __shfl_xor_sync(0xffffffffu, psum, 2);
        l_i = l_i * alpha + psum;
        m_i = m_new;
        #pragma unroll
        for (int i = 0; i < 16; i++) acc[i] *= alpha;
        __syncwarp();
        #pragma unroll
        for (int i = 0; i < 16; i++) {
            int d = c4 * 16 + i;
            float s = 0.f;
            #pragma unroll 8
            for (int j = 0; j < 32; j++) s += Ps[r][j] * Vs[j][d];
            acc[i] += s;
        }
        __syncthreads();
    }
    float inv = 1.f / l_i;
    float* ob = g_attn + (size_t)((b * S_ + q0 + r)) * H_ + (size_t)h * HD_;
    #pragma unroll
    for (int i = 0; i < 16; i++) ob[c4 * 16 + i] = acc[i] * inv;
}

// ---------------- residual + rmsnorm ---------------------------------------
__global__ __launch_bounds__(256)
void resid_rms(const float* __restrict__ a, const float* __restrict__ b,
               float* __restrict__ o) {
    const int t = blockIdx.x;
    float v[4]; float ss = 0.f;
    #pragma unroll
    for (int i = 0; i < 4; i++) {
        int j = i * 256 + threadIdx.x;
        float s = a[(size_t)t * H_ + j] + b[(size_t)t * H_ + j];
        v[i] = s; ss += s * s;
    }
    ss = block_sum256(ss);
    float inv = rsqrtf(ss * (1.f / H_) + EPS_);
    #pragma unroll
    for (int i = 0; i < 4; i++) {
        int j = i * 256 + threadIdx.x;
        o[(size_t)t * H_ + j] = v[i] * inv;
    }
}

// ---------------- routing ---------------------------------------------------
__global__ void zero_small() {
    int i = threadIdx.x;
    if (i < E_) { g_Pi[i] = 0.f; g_cnt[i] = 0; }
    if (i < D_)   g_comm[i] = 0.f;
}

__global__ void routing_kernel(const float* __restrict__ Wr) {
    const int t = blockIdx.x;
    const int e = threadIdx.x;   // 32 threads
    const float* xr = g_h1 + (size_t)t * H_;
    float logit = 0.f;
    for (int j = 0; j < H_; j++) logit += xr[j] * Wr[(size_t)j * E_ + e];
    float m = logit;
    #pragma unroll
    for (int o = 16; o; o >>= 1) m = fmaxf(m, __shfl_xor_sync(0xffffffffu, m, o));
    float ex = expf(logit - m);
    float s = ex;
    #pragma unroll
    for (int o = 16; o; o >>= 1) s += __shfl_xor_sync(0xffffffffu, s, o);
    float prob = ex / s;
    atomicAdd(&g_Pi[e], prob);
    __shared__ float sp[E_];
    sp[e] = prob;
    __syncwarp();
    if (e == 0) {
        float ds[D_];
        #pragma unroll
        for (int d = 0; d < D_; d++)
            ds[d] = sp[4 * d] + sp[4 * d + 1] + sp[4 * d + 2] + sp[4 * d + 3];
        bool dsel[D_] = {};
        for (int rsel = 0; rsel < KD_; rsel++) {
            int best = -1; float bv = -1e30f;
            for (int d = 0; d < D_; d++)
                if (!dsel[d] && ds[d] > bv) { bv = ds[d]; best = d; }
            dsel[best] = true;
        }
        float masked[E_];
        #pragma unroll
        for (int i = 0; i < E_; i++)
            masked[i] = dsel[i >> 2] ? sp[i] : -1e30f;
        int   iv[K_]; float wv[K_];
        for (int rsel = 0; rsel < K_; rsel++) {
            int best = 0; float bv = -1e31f;
            for (int i = 0; i < E_; i++)
                if (masked[i] > bv) { bv = masked[i]; best = i; }
            iv[rsel] = best; wv[rsel] = bv;
            masked[best] = -1e31f;
        }
        float mm = wv[0];
        float ssum = 0.f;
        #pragma unroll
        for (int rsel = 0; rsel < K_; rsel++) { wv[rsel] = expf(wv[rsel] - mm); ssum += wv[rsel]; }
        bool hit[D_] = {};
        #pragma unroll
        for (int rsel = 0; rsel < K_; rsel++) hit[iv[rsel] >> 2] = true;
        for (int d = 0; d < D_; d++)
            if (hit[d]) atomicAdd(&g_comm[d], 1.0f);
        #pragma unroll
        for (int rsel = 0; rsel < K_; rsel++) {
            int idx = t * K_ + rsel;
            g_sel_e[idx] = iv[rsel];
            g_sel_w[idx] = wv[rsel] / ssum;
            atomicAdd(&g_cnt[iv[rsel]], 1);
        }
    }
}

__global__ void offsets_kernel() {
    if (threadIdx.x == 0) {
        int s = 0;
        for (int e = 0; e < E_; e++) { g_off[e] = s; g_cur[e] = s; s += g_cnt[e]; }
    }
}

__global__ void scatter_kernel() {
    int i = blockIdx.x * 256 + threadIdx.x;
    if (i >= TK_) return;
    int e = g_sel_e[i];
    int pos = atomicAdd(&g_cur[e], 1);
    g_ltok[pos]  = i / K_;
    g_lslot[pos] = i;
    g_lw[pos]    = g_sel_w[i];
}

// ---------------- final combine + rmsnorm + aux ------------------------------
__global__ __launch_bounds__(256)
void final_kernel(float* __restrict__ out) {
    const int t = blockIdx.x;
    float v[4]; float ss = 0.f;
    #pragma unroll
    for (int i = 0; i < 4; i++) {
        int j = i * 256 + threadIdx.x;
        float s = g_h1[(size_t)t * H_ + j] + g_sout[(size_t)t * H_ + j];
        #pragma unroll
        for (int k = 0; k < K_; k++)
            s += g_rdwn[(size_t)(t * K_ + k) * H_ + j];
        v[i] = s; ss += s * s;
    }
    ss = block_sum256(ss);
    float inv = rsqrtf(ss * (1.f / H_) + EPS_);
    #pragma unroll
    for (int i = 0; i < 4; i++) {
        int j = i * 256 + threadIdx.x;
        out[(size_t)t * H_ + j] = v[i] * inv;
    }
}

__global__ void aux_kernel(float* out, int out_size) {
    if (out_size <= T_ * H_) return;
    const float fTK = (float)TK_ + 1e-10f;
    float fi[E_], Pi[E_];
    float s1 = 0.f;
    for (int e = 0; e < E_; e++) {
        fi[e] = (float)g_cnt[e] / fTK;
        Pi[e] = g_Pi[e] / (float)T_;
        s1 += fi[e] * Pi[e];
    }
    float eb = fminf(s1 * 0.003f, 10.f);
    float dP[D_];
    float s2 = 0.f;
    for (int d = 0; d < D_; d++) {
        float df = (fi[4*d] + fi[4*d+1] + fi[4*d+2] + fi[4*d+3]) * 0.25f;
        dP[d]    = Pi[4*d] + Pi[4*d+1] + Pi[4*d+2] + Pi[4*d+3];
        s2 += df * dP[d];
    }
    float db = fminf(s2 * 0.05f, 10.f);
    float s3 = 0.f;
    for (int d = 0; d < D_; d++) {
        float fc = g_comm[d] / ((float)(T_ * KD_) + 1e-10f);
        s3 += fc * dP[d];
    }
    float cb = fminf(s3 * 0.02f, 10.f);
    out[T_ * H_] = eb + db + cb;
}

// ---------------- host driver ------------------------------------------------
extern "C" void kernel_launch(void* const* d_in, const int* in_sizes, int n_in,
                              void* d_out, int out_size) {
    const float* x     = (const float*)d_in[0];
    const float* Wqkv  = (const float*)d_in[1];
    const float* Wo    = (const float*)d_in[2];
    const float* Wgu_s = (const float*)d_in[3];
    const float* Wd_s  = (const float*)d_in[4];
    const float* Wr    = (const float*)d_in[5];
    const float* Wgu   = (const float*)d_in[6];
    const float* Wd    = (const float*)d_in[7];
    float* out = (float*)d_out;

    float *p_qkv, *p_attn, *p_tmp, *p_h1, *p_sgu;
    cudaGetSymbolAddress((void**)&p_qkv,  g_qkv);
    cudaGetSymbolAddress((void**)&p_attn, g_attn);
    cudaGetSymbolAddress((void**)&p_tmp,  g_tmp);
    cudaGetSymbolAddress((void**)&p_h1,   g_h1);
    cudaGetSymbolAddress((void**)&p_sgu,  g_sgu);

    zero_small<<<1, 64>>>();

    // qkv = x @ Wqkv  (1024 x 3072 x 1024)
    mma_dense<<<dim3(3 * H_ / 128, T_ / 128), 256>>>(x, Wqkv, p_qkv, H_, 3 * H_, 0);

    // attention
    flash_attn<<<dim3(S_ / 64, NH_, B_), 256>>>();

    // proj = attn @ Wo, h1 = rmsnorm(x + proj)
    mma_dense<<<dim3(H_ / 128, T_ / 128), 256>>>(p_attn, Wo, p_tmp, H_, H_, 0);
    resid_rms<<<T_, 256>>>(x, p_tmp, p_h1);

    // shared experts (2): up GEMM, then down GEMM with fused SwiGLU
    for (int e = 0; e < 2; e++) {
        mma_dense<<<dim3(2 * I_ / 128, T_ / 128), 256>>>(
            p_h1, Wgu_s + (size_t)e * H_ * 2 * I_, p_sgu, H_, 2 * I_, 0);
        mma_shared_down<<<dim3(H_ / 128, T_ / 128), 256>>>(
            Wd_s + (size_t)e * I_ * H_, e);
    }

    // routing + sparse dispatch
    routing_kernel<<<T_, 32>>>(Wr);
    offsets_kernel<<<1, 32>>>();
    scatter_kernel<<<(TK_ + 255) / 256, 256>>>();

    // routed up-proj (gathered) and down-proj (fused SwiGLU, weighted scatter)
    mma_up_routed<<<dim3(2 * I_ / 128, T_ / 64, E_), 256>>>(Wgu);
    mma_down_routed<<<dim3(H_ / 128, T_ / 64, E_), 256>>>(Wd);

    // final residual + rmsnorm + aux
    final_kernel<<<T_, 256>>>(out);
    aux_kernel<<<1, 1>>>(out, out_size);
}

// round 6
// speedup vs baseline: 2.0170x; 1.1473x over previous
#include <cuda_runtime.h>
#include <cuda_bf16.h>
#include <math.h>
#include <stdint.h>

// ---------------- problem constants ----------------
#define B_   2
#define S_   512
#define T_   1024          // B*S tokens
#define H_   1024
#define NH_  16
#define HD_  64
#define E_   32
#define D_   8
#define K_   6
#define KD_  3
#define I_   1536
#define EPS_ 1e-5f
#define TK_  (T_*K_)       // 6144 assignments

// ---------------- device scratch (static, allowed) ----------------
__device__ float g_qkv [T_*3*H_];
__device__ float g_attn[T_*H_];
__device__ float g_tmp [2*T_*H_];     // split-K partials for Wo
__device__ float g_h1  [T_*H_];
__device__ float g_sgu [2*T_*2*I_];   // shared-expert gate/up, per expert
__device__ float g_sdwn[2*T_*H_];     // shared-expert down output, per expert
__device__ float g_rgu [TK_*2*I_];    // routed gate/up
__device__ float g_rdwn[TK_*H_];      // per-slot routed output

__device__ float g_Pi  [E_];
__device__ float g_comm[D_];
__device__ int   g_cnt [E_];
__device__ int   g_off [E_];
__device__ int   g_cur [E_];
__device__ int   g_sel_e[TK_];
__device__ float g_sel_w[TK_];
__device__ int   g_ltok [TK_];
__device__ int   g_lslot[TK_];
__device__ float g_lw   [TK_];

// ---------------- helpers ----------------
__device__ __forceinline__ float silu1(float g) { return g / (1.f + expf(-g)); }

__device__ __forceinline__ float block_sum256(float v) {
    __shared__ float red[8];
    __shared__ float tot;
    #pragma unroll
    for (int o = 16; o; o >>= 1) v += __shfl_xor_sync(0xffffffffu, v, o);
    if ((threadIdx.x & 31) == 0) red[threadIdx.x >> 5] = v;
    __syncthreads();
    if (threadIdx.x < 8) {
        float s = red[threadIdx.x];
        #pragma unroll
        for (int o = 4; o; o >>= 1) s += __shfl_xor_sync(0xffu, s, o);
        if (threadIdx.x == 0) tot = s;
    }
    __syncthreads();
    return tot;
}

// ---------------- mma/ldmatrix primitives -----------------------------------
__device__ __forceinline__ uint32_t smem_u32(const void* p) {
    return (uint32_t)__cvta_generic_to_shared(p);
}
__device__ __forceinline__ void ldm_x4(uint32_t r[4], uint32_t addr) {
    asm volatile("ldmatrix.sync.aligned.m8n8.x4.shared.b16 {%0,%1,%2,%3},[%4];"
        : "=r"(r[0]), "=r"(r[1]), "=r"(r[2]), "=r"(r[3]) : "r"(addr));
}
__device__ __forceinline__ void ldm_x4t(uint32_t r[4], uint32_t addr) {
    asm volatile("ldmatrix.sync.aligned.m8n8.x4.trans.shared.b16 {%0,%1,%2,%3},[%4];"
        : "=r"(r[0]), "=r"(r[1]), "=r"(r[2]), "=r"(r[3]) : "r"(addr));
}
__device__ __forceinline__ void mma_bf16(float c[4], const uint32_t a[4],
                                         uint32_t b0, uint32_t b1) {
    asm volatile(
        "mma.sync.aligned.m16n8k16.row.col.f32.bf16.bf16.f32 "
        "{%0,%1,%2,%3},{%4,%5,%6,%7},{%8,%9},{%0,%1,%2,%3};"
        : "+f"(c[0]), "+f"(c[1]), "+f"(c[2]), "+f"(c[3])
        : "r"(a[0]), "r"(a[1]), "r"(a[2]), "r"(a[3]), "r"(b0), "r"(b1));
}

// split fp32 pair into bf16 hi + lo pair
__device__ __forceinline__ void split2(float2 v, __nv_bfloat162& h, __nv_bfloat162& l) {
    h = __float22bfloat162_rn(v);
    float2 r = make_float2(v.x - __bfloat162float(h.x), v.y - __bfloat162float(h.y));
    l = __float22bfloat162_rn(r);
}
__device__ __forceinline__ void stage8(__nv_bfloat16* dh, __nv_bfloat16* dl,
                                       float4 f0, float4 f1) {
    __nv_bfloat162 h[4], l[4];
    split2(make_float2(f0.x, f0.y), h[0], l[0]);
    split2(make_float2(f0.z, f0.w), h[1], l[1]);
    split2(make_float2(f1.x, f1.y), h[2], l[2]);
    split2(make_float2(f1.z, f1.w), h[3], l[3]);
    *(uint4*)dh = *(uint4*)h;
    *(uint4*)dl = *(uint4*)l;
}
__device__ __forceinline__ void stage4(__nv_bfloat16* dh, __nv_bfloat16* dl, float4 f0) {
    __nv_bfloat162 h[2], l[2];
    split2(make_float2(f0.x, f0.y), h[0], l[0]);
    split2(make_float2(f0.z, f0.w), h[1], l[1]);
    *(uint2*)dh = *(uint2*)h;
    *(uint2*)dl = *(uint2*)l;
}

// A-smem pitch 24 halfs (48B), B-smem pitch 136 halfs: ldmatrix conflict-free
#define AP_ 24
#define BP_ 136

// One k16 step of the 3-term split GEMM for one warp (BM=64 config: NF=4).
// warp layout: wm in {0,1} (32 rows each), wn in {0..3} (32 cols each).
__device__ __forceinline__ void step64(
    const __nv_bfloat16* Ah, const __nv_bfloat16* Al,
    const __nv_bfloat16* Bh, const __nv_bfloat16* Bl,
    int wm, int wn, int lane, float (*acc)[4])
{
    constexpr int NF = 4;
    uint32_t ah[2][4], al[2][4];
    const int arow = lane & 15, acol = (lane >> 4) * 8;
    #pragma unroll
    for (int mf = 0; mf < 2; mf++) {
        int off = (wm * 32 + mf * 16 + arow) * AP_ + acol;
        ldm_x4(ah[mf], smem_u32(Ah + off));
        ldm_x4(al[mf], smem_u32(Al + off));
    }
    const int bkr = lane & 15;
    const int bnl = (lane >> 4) * 8;
    #pragma unroll
    for (int nf2 = 0; nf2 < NF / 2; nf2++) {
        int off = bkr * BP_ + wn * (NF * 8) + nf2 * 16 + bnl;
        uint32_t bh[4], bl4[4];
        ldm_x4t(bh,  smem_u32(Bh + off));
        ldm_x4t(bl4, smem_u32(Bl + off));
        #pragma unroll
        for (int mf = 0; mf < 2; mf++) {
            float* c0 = acc[mf * NF + nf2 * 2 + 0];
            float* c1 = acc[mf * NF + nf2 * 2 + 1];
            mma_bf16(c0, ah[mf], bh[0],  bh[1]);
            mma_bf16(c0, ah[mf], bl4[0], bl4[1]);
            mma_bf16(c0, al[mf], bh[0],  bh[1]);
            mma_bf16(c1, ah[mf], bh[2],  bh[3]);
            mma_bf16(c1, ah[mf], bl4[2], bl4[3]);
            mma_bf16(c1, al[mf], bh[2],  bh[3]);
        }
    }
}

#define GEMM64_SMEM \
    __shared__ __align__(16) __nv_bfloat16 sAh[2][64][AP_]; \
    __shared__ __align__(16) __nv_bfloat16 sAl[2][64][AP_]; \
    __shared__ __align__(16) __nv_bfloat16 sBh[2][16][BP_]; \
    __shared__ __align__(16) __nv_bfloat16 sBl[2][16][BP_];

// ============================================================================
// Batched dense GEMM: C[z] = A @ B[z].  BM=64, BN=128, BK=16.
// grid=(N/128, M/64, nz), block=256. z applies strides to B and C.
// ============================================================================
__global__ __launch_bounds__(256)
void mma_d64_batch(const float* __restrict__ A, const float* __restrict__ Bw,
                   float* __restrict__ C, int Kd, int N,
                   size_t bStride, size_t cStride)
{
    constexpr int NF = 4;
    GEMM64_SMEM
    const int tid = threadIdx.x, lane = tid & 31, wid = tid >> 5;
    const int wm = wid & 1, wn = wid >> 1;
    const int m0 = blockIdx.y * 64, n0 = blockIdx.x * 128;
    const float* Bz = Bw + (size_t)blockIdx.z * bStride;
    float* Cz = C + (size_t)blockIdx.z * cStride;

    const int ar = tid >> 2, akc = (tid & 3) * 4;
    const int bk = tid >> 4, bnc = (tid & 15) * 8;
    const float* Ag = A + (size_t)(m0 + ar) * Kd + akc;
    const float* Bg = Bz + (size_t)bk * N + n0 + bnc;

    float acc[2 * NF][4];
    #pragma unroll
    for (int i = 0; i < 2 * NF; i++)
        #pragma unroll
        for (int j = 0; j < 4; j++) acc[i][j] = 0.f;

    float4 fa = *(const float4*)Ag;
    float4 fb0 = *(const float4*)Bg, fb1 = *(const float4*)(Bg + 4);
    stage4(&sAh[0][ar][akc], &sAl[0][ar][akc], fa);
    stage8(&sBh[0][bk][bnc], &sBl[0][bk][bnc], fb0, fb1);
    __syncthreads();

    const int nK = Kd >> 4;
    int buf = 0;
    for (int kt = 0; kt < nK; kt++) {
        const bool nxt = (kt + 1) < nK;
        if (nxt) {
            int k0 = (kt + 1) << 4;
            fa = *(const float4*)(Ag + k0);
            fb0 = *(const float4*)(Bg + (size_t)k0 * N);
            fb1 = *(const float4*)(Bg + (size_t)k0 * N + 4);
        }
        step64(&sAh[buf][0][0], &sAl[buf][0][0],
               &sBh[buf][0][0], &sBl[buf][0][0], wm, wn, lane, acc);
        if (nxt) {
            int nb = buf ^ 1;
            stage4(&sAh[nb][ar][akc], &sAl[nb][ar][akc], fa);
            stage8(&sBh[nb][bk][bnc], &sBl[nb][bk][bnc], fb0, fb1);
        }
        __syncthreads();
        buf ^= 1;
    }

    #pragma unroll
    for (int mf = 0; mf < 2; mf++)
        #pragma unroll
        for (int nf = 0; nf < NF; nf++) {
            float* c = acc[mf * NF + nf];
            int r0  = m0 + wm * 32 + mf * 16 + (lane >> 2);
            int col = n0 + wn * (NF * 8) + nf * 8 + (lane & 3) * 2;
            float* p0 = Cz + (size_t)r0 * N + col;
            float* p1 = Cz + (size_t)(r0 + 8) * N + col;
            p0[0] = c[0]; p0[1] = c[1]; p1[0] = c[2]; p1[1] = c[3];
        }
}

// ============================================================================
// Split-K dense GEMM (for Wo): z in {0,1} computes half the K range,
// writing partials to C + z*T*H. grid=(N/128, M/64, 2).
// ============================================================================
__global__ __launch_bounds__(256)
void mma_d64_splitk(const float* __restrict__ A, const float* __restrict__ Bw,
                    float* __restrict__ C, int Kd, int N)
{
    constexpr int NF = 4;
    GEMM64_SMEM
    const int tid = threadIdx.x, lane = tid & 31, wid = tid >> 5;
    const int wm = wid & 1, wn = wid >> 1;
    const int m0 = blockIdx.y * 64, n0 = blockIdx.x * 128;
    const int kHalf = Kd >> 1;
    const int kOff = blockIdx.z * kHalf;
    float* Cz = C + (size_t)blockIdx.z * T_ * H_;

    const int ar = tid >> 2, akc = (tid & 3) * 4;
    const int bk = tid >> 4, bnc = (tid & 15) * 8;
    const float* Ag = A + (size_t)(m0 + ar) * Kd + kOff + akc;
    const float* Bg = Bw + (size_t)(kOff + bk) * N + n0 + bnc;

    float acc[2 * NF][4];
    #pragma unroll
    for (int i = 0; i < 2 * NF; i++)
        #pragma unroll
        for (int j = 0; j < 4; j++) acc[i][j] = 0.f;

    float4 fa = *(const float4*)Ag;
    float4 fb0 = *(const float4*)Bg, fb1 = *(const float4*)(Bg + 4);
    stage4(&sAh[0][ar][akc], &sAl[0][ar][akc], fa);
    stage8(&sBh[0][bk][bnc], &sBl[0][bk][bnc], fb0, fb1);
    __syncthreads();

    const int nK = kHalf >> 4;
    int buf = 0;
    for (int kt = 0; kt < nK; kt++) {
        const bool nxt = (kt + 1) < nK;
        if (nxt) {
            int k0 = (kt + 1) << 4;
            fa = *(const float4*)(Ag + k0);
            fb0 = *(const float4*)(Bg + (size_t)k0 * N);
            fb1 = *(const float4*)(Bg + (size_t)k0 * N + 4);
        }
        step64(&sAh[buf][0][0], &sAl[buf][0][0],
               &sBh[buf][0][0], &sBl[buf][0][0], wm, wn, lane, acc);
        if (nxt) {
            int nb = buf ^ 1;
            stage4(&sAh[nb][ar][akc], &sAl[nb][ar][akc], fa);
            stage8(&sBh[nb][bk][bnc], &sBl[nb][bk][bnc], fb0, fb1);
        }
        __syncthreads();
        buf ^= 1;
    }

    #pragma unroll
    for (int mf = 0; mf < 2; mf++)
        #pragma unroll
        for (int nf = 0; nf < NF; nf++) {
            float* c = acc[mf * NF + nf];
            int r0  = m0 + wm * 32 + mf * 16 + (lane >> 2);
            int col = n0 + wn * (NF * 8) + nf * 8 + (lane & 3) * 2;
            float* p0 = Cz + (size_t)r0 * N + col;
            float* p1 = Cz + (size_t)(r0 + 8) * N + col;
            p0[0] = c[0]; p0[1] = c[1]; p1[0] = c[2]; p1[1] = c[3];
        }
}

// ============================================================================
// Shared-expert down GEMM, batched over z=e: A = silu(g)*u from g_sgu[e],
// C = g_sdwn[e]. grid=(H/128, T/64, 2).
// ============================================================================
__global__ __launch_bounds__(256)
void mma_shared_down(const float* __restrict__ Wd_s)
{
    constexpr int NF = 4;
    const int N = H_, Kd = I_;
    GEMM64_SMEM
    const int tid = threadIdx.x, lane = tid & 31, wid = tid >> 5;
    const int wm = wid & 1, wn = wid >> 1;
    const int m0 = blockIdx.y * 64, n0 = blockIdx.x * 128;
    const int e = blockIdx.z;
    const float* Az = g_sgu + (size_t)e * T_ * 2 * I_;
    const float* Bz = Wd_s + (size_t)e * I_ * H_;
    float* Cz = g_sdwn + (size_t)e * T_ * H_;

    const int ar = tid >> 2, akc = (tid & 3) * 4;
    const int bk = tid >> 4, bnc = (tid & 15) * 8;
    const float* Gg = Az + (size_t)(m0 + ar) * (2 * I_) + akc;
    const float* Bg = Bz + (size_t)bk * N + n0 + bnc;

    float acc[2 * NF][4];
    #pragma unroll
    for (int i = 0; i < 2 * NF; i++)
        #pragma unroll
        for (int j = 0; j < 4; j++) acc[i][j] = 0.f;

    float4 fa;
    {
        float4 gg = *(const float4*)Gg, uu = *(const float4*)(Gg + I_);
        fa = make_float4(silu1(gg.x)*uu.x, silu1(gg.y)*uu.y,
                         silu1(gg.z)*uu.z, silu1(gg.w)*uu.w);
    }
    float4 fb0 = *(const float4*)Bg, fb1 = *(const float4*)(Bg + 4);
    stage4(&sAh[0][ar][akc], &sAl[0][ar][akc], fa);
    stage8(&sBh[0][bk][bnc], &sBl[0][bk][bnc], fb0, fb1);
    __syncthreads();

    const int nK = Kd >> 4;
    int buf = 0;
    for (int kt = 0; kt < nK; kt++) {
        const bool nxt = (kt + 1) < nK;
        if (nxt) {
            int k0 = (kt + 1) << 4;
            float4 gg = *(const float4*)(Gg + k0), uu = *(const float4*)(Gg + k0 + I_);
            fa = make_float4(silu1(gg.x)*uu.x, silu1(gg.y)*uu.y,
                             silu1(gg.z)*uu.z, silu1(gg.w)*uu.w);
            fb0 = *(const float4*)(Bg + (size_t)k0 * N);
            fb1 = *(const float4*)(Bg + (size_t)k0 * N + 4);
        }
        step64(&sAh[buf][0][0], &sAl[buf][0][0],
               &sBh[buf][0][0], &sBl[buf][0][0], wm, wn, lane, acc);
        if (nxt) {
            int nb = buf ^ 1;
            stage4(&sAh[nb][ar][akc], &sAl[nb][ar][akc], fa);
            stage8(&sBh[nb][bk][bnc], &sBl[nb][bk][bnc], fb0, fb1);
        }
        __syncthreads();
        buf ^= 1;
    }

    #pragma unroll
    for (int mf = 0; mf < 2; mf++)
        #pragma unroll
        for (int nf = 0; nf < NF; nf++) {
            float* c = acc[mf * NF + nf];
            int r0  = m0 + wm * 32 + mf * 16 + (lane >> 2);
            int col = n0 + wn * (NF * 8) + nf * 8 + (lane & 3) * 2;
            float* p0 = Cz + (size_t)r0 * N + col;
            float* p1 = Cz + (size_t)(r0 + 8) * N + col;
            p0[0] = c[0]; p0[1] = c[1]; p1[0] = c[2]; p1[1] = c[3];
        }
}

// ============================================================================
// Routed up GEMM: BM=64, gathered A rows from g_h1. grid=(2I/128, T/64, E).
// ============================================================================
__global__ __launch_bounds__(256)
void mma_up_routed(const float* __restrict__ Wgu)
{
    constexpr int NF = 4;
    const int e = blockIdx.z;
    const int cnt = g_cnt[e];
    const int m0 = blockIdx.y * 64;
    if (m0 >= cnt) return;
    const int off = g_off[e];
    const int n0 = blockIdx.x * 128;
    const int N = 2 * I_, Kd = H_;
    const float* __restrict__ Bw = Wgu + (size_t)e * H_ * 2 * I_;

    GEMM64_SMEM
    const int tid = threadIdx.x, lane = tid & 31, wid = tid >> 5;
    const int wm = wid & 1, wn = wid >> 1;
    const int ar = tid >> 2, akc = (tid & 3) * 4;
    const int bk = tid >> 4, bnc = (tid & 15) * 8;

    const int tok = (m0 + ar < cnt) ? g_ltok[off + m0 + ar] : -1;
    const float* Ag = (tok >= 0) ? (g_h1 + (size_t)tok * H_ + akc) : g_h1;
    const float* Bg = Bw + (size_t)bk * N + n0 + bnc;

    float acc[2 * NF][4];
    #pragma unroll
    for (int i = 0; i < 2 * NF; i++)
        #pragma unroll
        for (int j = 0; j < 4; j++) acc[i][j] = 0.f;

    float4 fa = (tok >= 0) ? *(const float4*)Ag : make_float4(0.f,0.f,0.f,0.f);
    float4 fb0 = *(const float4*)Bg, fb1 = *(const float4*)(Bg + 4);
    stage4(&sAh[0][ar][akc], &sAl[0][ar][akc], fa);
    stage8(&sBh[0][bk][bnc], &sBl[0][bk][bnc], fb0, fb1);
    __syncthreads();

    const int nK = Kd >> 4;
    int buf = 0;
    for (int kt = 0; kt < nK; kt++) {
        const bool nxt = (kt + 1) < nK;
        if (nxt) {
            int k0 = (kt + 1) << 4;
            fa = (tok >= 0) ? *(const float4*)(Ag + k0) : make_float4(0.f,0.f,0.f,0.f);
            fb0 = *(const float4*)(Bg + (size_t)k0 * N);
            fb1 = *(const float4*)(Bg + (size_t)k0 * N + 4);
        }
        step64(&sAh[buf][0][0], &sAl[buf][0][0],
               &sBh[buf][0][0], &sBl[buf][0][0], wm, wn, lane, acc);
        if (nxt) {
            int nb = buf ^ 1;
            stage4(&sAh[nb][ar][akc], &sAl[nb][ar][akc], fa);
            stage8(&sBh[nb][bk][bnc], &sBl[nb][bk][bnc], fb0, fb1);
        }
        __syncthreads();
        buf ^= 1;
    }

    #pragma unroll
    for (int mf = 0; mf < 2; mf++)
        #pragma unroll
        for (int nf = 0; nf < NF; nf++) {
            float* c = acc[mf * NF + nf];
            int lr0 = m0 + wm * 32 + mf * 16 + (lane >> 2);
            int col = n0 + wn * (NF * 8) + nf * 8 + (lane & 3) * 2;
            if (lr0 < cnt) {
                float* p = g_rgu + (size_t)(off + lr0) * N + col;
                p[0] = c[0]; p[1] = c[1];
            }
            if (lr0 + 8 < cnt) {
                float* p = g_rgu + (size_t)(off + lr0 + 8) * N + col;
                p[0] = c[2]; p[1] = c[3];
            }
        }
}

// ============================================================================
// Routed down GEMM: BM=64, fused SwiGLU A from g_rgu, weighted scatter out.
// grid=(H/128, T/64, E).
// ============================================================================
__global__ __launch_bounds__(256)
void mma_down_routed(const float* __restrict__ Wd)
{
    constexpr int NF = 4;
    const int e = blockIdx.z;
    const int cnt = g_cnt[e];
    const int m0 = blockIdx.y * 64;
    if (m0 >= cnt) return;
    const int off = g_off[e];
    const int n0 = blockIdx.x * 128;
    const int N = H_, Kd = I_;
    const float* __restrict__ Bw = Wd + (size_t)e * I_ * H_;

    GEMM64_SMEM
    const int tid = threadIdx.x, lane = tid & 31, wid = tid >> 5;
    const int wm = wid & 1, wn = wid >> 1;
    const int ar = tid >> 2, akc = (tid & 3) * 4;
    const int bk = tid >> 4, bnc = (tid & 15) * 8;

    const bool aok = (m0 + ar) < cnt;
    const float* Ag = g_rgu + (size_t)(off + (aok ? m0 + ar : 0)) * (2 * I_) + akc;
    const float* Bg = Bw + (size_t)bk * N + n0 + bnc;

    float acc[2 * NF][4];
    #pragma unroll
    for (int i = 0; i < 2 * NF; i++)
        #pragma unroll
        for (int j = 0; j < 4; j++) acc[i][j] = 0.f;

    float4 fa = make_float4(0.f,0.f,0.f,0.f);
    if (aok) {
        float4 gg = *(const float4*)Ag, uu = *(const float4*)(Ag + I_);
        fa = make_float4(silu1(gg.x)*uu.x, silu1(gg.y)*uu.y,
                         silu1(gg.z)*uu.z, silu1(gg.w)*uu.w);
    }
    float4 fb0 = *(const float4*)Bg, fb1 = *(const float4*)(Bg + 4);
    stage4(&sAh[0][ar][akc], &sAl[0][ar][akc], fa);
    stage8(&sBh[0][bk][bnc], &sBl[0][bk][bnc], fb0, fb1);
    __syncthreads();

    const int nK = Kd >> 4;
    int buf = 0;
    for (int kt = 0; kt < nK; kt++) {
        const bool nxt = (kt + 1) < nK;
        if (nxt) {
            int k0 = (kt + 1) << 4;
            fa = make_float4(0.f,0.f,0.f,0.f);
            if (aok) {
                float4 gg = *(const float4*)(Ag + k0), uu = *(const float4*)(Ag + k0 + I_);
                fa = make_float4(silu1(gg.x)*uu.x, silu1(gg.y)*uu.y,
                                 silu1(gg.z)*uu.z, silu1(gg.w)*uu.w);
            }
            fb0 = *(const float4*)(Bg + (size_t)k0 * N);
            fb1 = *(const float4*)(Bg + (size_t)k0 * N + 4);
        }
        step64(&sAh[buf][0][0], &sAl[buf][0][0],
               &sBh[buf][0][0], &sBl[buf][0][0], wm, wn, lane, acc);
        if (nxt) {
            int nb = buf ^ 1;
            stage4(&sAh[nb][ar][akc], &sAl[nb][ar][akc], fa);
            stage8(&sBh[nb][bk][bnc], &sBl[nb][bk][bnc], fb0, fb1);
        }
        __syncthreads();
        buf ^= 1;
    }

    #pragma unroll
    for (int mf = 0; mf < 2; mf++)
        #pragma unroll
        for (int nf = 0; nf < NF; nf++) {
            float* c = acc[mf * NF + nf];
            int lr0 = m0 + wm * 32 + mf * 16 + (lane >> 2);
            int col = n0 + wn * (NF * 8) + nf * 8 + (lane & 3) * 2;
            if (lr0 < cnt) {
                int slot = g_lslot[off + lr0];
                float w  = g_lw[off + lr0];
                float* p = g_rdwn + (size_t)slot * H_ + col;
                p[0] = w * c[0]; p[1] = w * c[1];
            }
            if (lr0 + 8 < cnt) {
                int slot = g_lslot[off + lr0 + 8];
                float w  = g_lw[off + lr0 + 8];
                float* p = g_rdwn + (size_t)slot * H_ + col;
                p[0] = w * c[2]; p[1] = w * c[3];
            }
        }
}

// ---------------- flash attention (fp32, validated) --------------------------
__global__ __launch_bounds__(256)
void flash_attn() {
    __shared__ float Qs[64][68];
    __shared__ float Ks[32][68];
    __shared__ float Vs[32][68];
    __shared__ float Ps[64][36];
    const int q0 = blockIdx.x * 64;
    const int h  = blockIdx.y;
    const int b  = blockIdx.z;
    const int tid = threadIdx.x;
    const size_t rs = 3 * H_;
    const float* qb = g_qkv + (size_t)b * S_ * rs + (size_t)h * HD_;
    const float* kb = qb + H_;
    const float* vb = qb + 2 * H_;
    const float scale = 0.125f;
    for (int i = tid; i < 64 * 64; i += 256) {
        int r = i >> 6, d = i & 63;
        Qs[r][d] = qb[(size_t)(q0 + r) * rs + d] * scale;
    }
    const int r  = tid >> 2;
    const int c4 = tid & 3;
    float m_i = -1e30f, l_i = 0.f;
    float acc[16];
    #pragma unroll
    for (int i = 0; i < 16; i++) acc[i] = 0.f;
    __syncthreads();
    for (int kt = 0; kt < S_; kt += 32) {
        for (int i = tid; i < 32 * 64; i += 256) {
            int rr = i >> 6, d = i & 63;
            Ks[rr][d] = kb[(size_t)(kt + rr) * rs + d];
            Vs[rr][d] = vb[(size_t)(kt + rr) * rs + d];
        }
        __syncthreads();
        float sc[8];
        float mx = -1e30f;
        const float4* qrow = (const float4*)&Qs[r][0];
        #pragma unroll
        for (int jj = 0; jj < 8; jj++) {
            int j = c4 * 8 + jj;
            const float4* krow = (const float4*)&Ks[j][0];
            float sv = 0.f;
            #pragma unroll
            for (int dv = 0; dv < 16; dv++) {
                float4 a = qrow[dv], bq = krow[dv];
                sv += a.x * bq.x + a.y * bq.y + a.z * bq.z + a.w * bq.w;
            }
            sc[jj] = sv; mx = fmaxf(mx, sv);
        }
        mx = fmaxf(mx, __shfl_xor_sync(0xffffffffu, mx, 1));
        mx = fmaxf(mx, __shfl_xor_sync(0xffffffffu, mx, 2));
        float m_new = fmaxf(m_i, mx);
        float alpha = expf(m_i - m_new);
        float psum = 0.f;
        #pragma unroll
        for (int jj = 0; jj < 8; jj++) {
            float p = expf(sc[jj] - m_new);
            Ps[r][c4 * 8 + jj] = p;
            psum += p;
        }
        psum += __shfl_xor_sync(0xffffffffu, psum, 1);
        psum += __shfl_xor_sync(0xffffffffu, psum, 2);
        l_i = l_i * alpha + psum;
        m_i = m_new;
        #pragma unroll
        for (int i = 0; i < 16; i++) acc[i] *= alpha;
        __syncwarp();
        #pragma unroll
        for (int i = 0; i < 16; i++) {
            int d = c4 * 16 + i;
            float s = 0.f;
            #pragma unroll 8
            for (int j = 0; j < 32; j++) s += Ps[r][j] * Vs[j][d];
            acc[i] += s;
        }
        __syncthreads();
    }
    float inv = 1.f / l_i;
    float* ob = g_attn + (size_t)((b * S_ + q0 + r)) * H_ + (size_t)h * HD_;
    #pragma unroll
    for (int i = 0; i < 16; i++) ob[c4 * 16 + i] = acc[i] * inv;
}

// ---------------- residual + rmsnorm over 3-way sum --------------------------
__global__ __launch_bounds__(256)
void resid_rms3(const float* __restrict__ a, const float* __restrict__ b0,
                const float* __restrict__ b1, float* __restrict__ o) {
    const int t = blockIdx.x;
    float v[4]; float ss = 0.f;
    #pragma unroll
    for (int i = 0; i < 4; i++) {
        int j = i * 256 + threadIdx.x;
        float s = a[(size_t)t * H_ + j] + b0[(size_t)t * H_ + j] + b1[(size_t)t * H_ + j];
        v[i] = s; ss += s * s;
    }
    ss = block_sum256(ss);
    float inv = rsqrtf(ss * (1.f / H_) + EPS_);
    #pragma unroll
    for (int i = 0; i < 4; i++) {
        int j = i * 256 + threadIdx.x;
        o[(size_t)t * H_ + j] = v[i] * inv;
    }
}

// ---------------- routing ---------------------------------------------------
__global__ void zero_small() {
    int i = threadIdx.x;
    if (i < E_) { g_Pi[i] = 0.f; g_cnt[i] = 0; }
    if (i < D_)   g_comm[i] = 0.f;
}

__global__ void routing_kernel(const float* __restrict__ Wr) {
    const int t = blockIdx.x;
    const int e = threadIdx.x;   // 32 threads
    const float* xr = g_h1 + (size_t)t * H_;
    float logit = 0.f;
    for (int j = 0; j < H_; j++) logit += xr[j] * Wr[(size_t)j * E_ + e];
    float m = logit;
    #pragma unroll
    for (int o = 16; o; o >>= 1) m = fmaxf(m, __shfl_xor_sync(0xffffffffu, m, o));
    float ex = expf(logit - m);
    float s = ex;
    #pragma unroll
    for (int o = 16; o; o >>= 1) s += __shfl_xor_sync(0xffffffffu, s, o);
    float prob = ex / s;
    atomicAdd(&g_Pi[e], prob);
    __shared__ float sp[E_];
    sp[e] = prob;
    __syncwarp();
    if (e == 0) {
        float ds[D_];
        #pragma unroll
        for (int d = 0; d < D_; d++)
            ds[d] = sp[4 * d] + sp[4 * d + 1] + sp[4 * d + 2] + sp[4 * d + 3];
        bool dsel[D_] = {};
        for (int rsel = 0; rsel < KD_; rsel++) {
            int best = -1; float bv = -1e30f;
            for (int d = 0; d < D_; d++)
                if (!dsel[d] && ds[d] > bv) { bv = ds[d]; best = d; }
            dsel[best] = true;
        }
        float masked[E_];
        #pragma unroll
        for (int i = 0; i < E_; i++)
            masked[i] = dsel[i >> 2] ? sp[i] : -1e30f;
        int   iv[K_]; float wv[K_];
        for (int rsel = 0; rsel < K_; rsel++) {
            int best = 0; float bv = -1e31f;
            for (int i = 0; i < E_; i++)
                if (masked[i] > bv) { bv = masked[i]; best = i; }
            iv[rsel] = best; wv[rsel] = bv;
            masked[best] = -1e31f;
        }
        float mm = wv[0];
        float ssum = 0.f;
        #pragma unroll
        for (int rsel = 0; rsel < K_; rsel++) { wv[rsel] = expf(wv[rsel] - mm); ssum += wv[rsel]; }
        bool hit[D_] = {};
        #pragma unroll
        for (int rsel = 0; rsel < K_; rsel++) hit[iv[rsel] >> 2] = true;
        for (int d = 0; d < D_; d++)
            if (hit[d]) atomicAdd(&g_comm[d], 1.0f);
        #pragma unroll
        for (int rsel = 0; rsel < K_; rsel++) {
            int idx = t * K_ + rsel;
            g_sel_e[idx] = iv[rsel];
            g_sel_w[idx] = wv[rsel] / ssum;
            atomicAdd(&g_cnt[iv[rsel]], 1);
        }
    }
}

__global__ void offsets_kernel() {
    if (threadIdx.x == 0) {
        int s = 0;
        for (int e = 0; e < E_; e++) { g_off[e] = s; g_cur[e] = s; s += g_cnt[e]; }
    }
}

__global__ void scatter_kernel() {
    int i = blockIdx.x * 256 + threadIdx.x;
    if (i >= TK_) return;
    int e = g_sel_e[i];
    int pos = atomicAdd(&g_cur[e], 1);
    g_ltok[pos]  = i / K_;
    g_lslot[pos] = i;
    g_lw[pos]    = g_sel_w[i];
}

// ---------------- final combine + rmsnorm + aux ------------------------------
__global__ __launch_bounds__(256)
void final_kernel(float* __restrict__ out) {
    const int t = blockIdx.x;
    float v[4]; float ss = 0.f;
    #pragma unroll
    for (int i = 0; i < 4; i++) {
        int j = i * 256 + threadIdx.x;
        float s = g_h1[(size_t)t * H_ + j]
                + g_sdwn[(size_t)t * H_ + j]
                + g_sdwn[(size_t)(T_ + t) * H_ + j];
        #pragma unroll
        for (int k = 0; k < K_; k++)
            s += g_rdwn[(size_t)(t * K_ + k) * H_ + j];
        v[i] = s; ss += s * s;
    }
    ss = block_sum256(ss);
    float inv = rsqrtf(ss * (1.f / H_) + EPS_);
    #pragma unroll
    for (int i = 0; i < 4; i++) {
        int j = i * 256 + threadIdx.x;
        out[(size_t)t * H_ + j] = v[i] * inv;
    }
}

__global__ void aux_kernel(float* out, int out_size) {
    if (out_size <= T_ * H_) return;
    const float fTK = (float)TK_ + 1e-10f;
    float fi[E_], Pi[E_];
    float s1 = 0.f;
    for (int e = 0; e < E_; e++) {
        fi[e] = (float)g_cnt[e] / fTK;
        Pi[e] = g_Pi[e] / (float)T_;
        s1 += fi[e] * Pi[e];
    }
    float eb = fminf(s1 * 0.003f, 10.f);
    float dP[D_];
    float s2 = 0.f;
    for (int d = 0; d < D_; d++) {
        float df = (fi[4*d] + fi[4*d+1] + fi[4*d+2] + fi[4*d+3]) * 0.25f;
        dP[d]    = Pi[4*d] + Pi[4*d+1] + Pi[4*d+2] + Pi[4*d+3];
        s2 += df * dP[d];
    }
    float db = fminf(s2 * 0.05f, 10.f);
    float s3 = 0.f;
    for (int d = 0; d < D_; d++) {
        float fc = g_comm[d] / ((float)(T_ * KD_) + 1e-10f);
        s3 += fc * dP[d];
    }
    float cb = fminf(s3 * 0.02f, 10.f);
    out[T_ * H_] = eb + db + cb;
}

// ---------------- host driver ------------------------------------------------
extern "C" void kernel_launch(void* const* d_in, const int* in_sizes, int n_in,
                              void* d_out, int out_size) {
    const float* x     = (const float*)d_in[0];
    const float* Wqkv  = (const float*)d_in[1];
    const float* Wo    = (const float*)d_in[2];
    const float* Wgu_s = (const float*)d_in[3];
    const float* Wd_s  = (const float*)d_in[4];
    const float* Wr    = (const float*)d_in[5];
    const float* Wgu   = (const float*)d_in[6];
    const float* Wd    = (const float*)d_in[7];
    float* out = (float*)d_out;

    float *p_qkv, *p_attn, *p_tmp, *p_h1, *p_sgu;
    cudaGetSymbolAddress((void**)&p_qkv,  g_qkv);
    cudaGetSymbolAddress((void**)&p_attn, g_attn);
    cudaGetSymbolAddress((void**)&p_tmp,  g_tmp);
    cudaGetSymbolAddress((void**)&p_h1,   g_h1);
    cudaGetSymbolAddress((void**)&p_sgu,  g_sgu);

    zero_small<<<1, 64>>>();

    // qkv = x @ Wqkv  (M=1024, N=3072, K=1024), grid 384
    mma_d64_batch<<<dim3(3 * H_ / 128, T_ / 64, 1), 256>>>(
        x, Wqkv, p_qkv, H_, 3 * H_, 0, 0);

    // attention
    flash_attn<<<dim3(S_ / 64, NH_, B_), 256>>>();

    // Wo with split-K=2, grid 256; h1 = rmsnorm(x + tmp0 + tmp1)
    mma_d64_splitk<<<dim3(H_ / 128, T_ / 64, 2), 256>>>(p_attn, Wo, p_tmp, H_, H_);
    resid_rms3<<<T_, 256>>>(x, p_tmp, p_tmp + (size_t)T_ * H_, p_h1);

    // shared experts, batched over z=2: up (grid 768), down fused-SwiGLU (grid 256)
    mma_d64_batch<<<dim3(2 * I_ / 128, T_ / 64, 2), 256>>>(
        p_h1, Wgu_s, p_sgu, H_, 2 * I_,
        (size_t)H_ * 2 * I_, (size_t)T_ * 2 * I_);
    mma_shared_down<<<dim3(H_ / 128, T_ / 64, 2), 256>>>(Wd_s);

    // routing + sparse dispatch
    routing_kernel<<<T_, 32>>>(Wr);
    offsets_kernel<<<1, 32>>>();
    scatter_kernel<<<(TK_ + 255) / 256, 256>>>();

    // routed up-proj (gathered) and down-proj (fused SwiGLU, weighted scatter)
    mma_up_routed<<<dim3(2 * I_ / 128, T_ / 64, E_), 256>>>(Wgu);
    mma_down_routed<<<dim3(H_ / 128, T_ / 64, E_), 256>>>(Wd);

    // final residual + rmsnorm + aux
    final_kernel<<<T_, 256>>>(out);
    aux_kernel<<<1, 1>>>(out, out_size);
}

// round 7
// speedup vs baseline: 2.2069x; 1.0942x over previous
#include <cuda_runtime.h>
#include <cuda_bf16.h>
#include <math.h>
#include <stdint.h>

// ---------------- problem constants ----------------
#define B_   2
#define S_   512
#define T_   1024
#define H_   1024
#define NH_  16
#define HD_  64
#define E_   32
#define D_   8
#define K_   6
#define KD_  3
#define I_   1536
#define EPS_ 1e-5f
#define TK_  (T_*K_)

// ---------------- device scratch ----------------
__device__ float g_qkv [T_*3*H_];
__device__ float g_attn[T_*H_];
__device__ float g_tmp [2*T_*H_];
__device__ float g_h1  [T_*H_];
__device__ float g_sgu [2*T_*2*I_];
__device__ float g_sdwn[2*T_*H_];
__device__ float g_rgu [TK_*2*I_];
__device__ float g_rdwn[TK_*H_];

__device__ float g_Pi  [E_];
__device__ float g_comm[D_];
__device__ int   g_cnt [E_];
__device__ int   g_off [E_];
__device__ int   g_cur [E_];
__device__ int   g_sel_e[TK_];
__device__ float g_sel_w[TK_];
__device__ int   g_ltok [TK_];
__device__ int   g_lslot[TK_];
__device__ float g_lw   [TK_];

__device__ __forceinline__ float silu1(float g) { return g / (1.f + expf(-g)); }

__device__ __forceinline__ float block_sum256(float v) {
    __shared__ float red[8];
    __shared__ float tot;
    #pragma unroll
    for (int o = 16; o; o >>= 1) v += __shfl_xor_sync(0xffffffffu, v, o);
    if ((threadIdx.x & 31) == 0) red[threadIdx.x >> 5] = v;
    __syncthreads();
    if (threadIdx.x < 8) {
        float s = red[threadIdx.x];
        #pragma unroll
        for (int o = 4; o; o >>= 1) s += __shfl_xor_sync(0xffu, s, o);
        if (threadIdx.x == 0) tot = s;
    }
    __syncthreads();
    return tot;
}

// ---------------- mma/ldmatrix primitives -----------------------------------
__device__ __forceinline__ uint32_t smem_u32(const void* p) {
    return (uint32_t)__cvta_generic_to_shared(p);
}
__device__ __forceinline__ void ldm_x4(uint32_t r[4], uint32_t addr) {
    asm volatile("ldmatrix.sync.aligned.m8n8.x4.shared.b16 {%0,%1,%2,%3},[%4];"
        : "=r"(r[0]), "=r"(r[1]), "=r"(r[2]), "=r"(r[3]) : "r"(addr));
}
__device__ __forceinline__ void ldm_x4t(uint32_t r[4], uint32_t addr) {
    asm volatile("ldmatrix.sync.aligned.m8n8.x4.trans.shared.b16 {%0,%1,%2,%3},[%4];"
        : "=r"(r[0]), "=r"(r[1]), "=r"(r[2]), "=r"(r[3]) : "r"(addr));
}
__device__ __forceinline__ void mma_bf16(float c[4], const uint32_t a[4],
                                         uint32_t b0, uint32_t b1) {
    asm volatile(
        "mma.sync.aligned.m16n8k16.row.col.f32.bf16.bf16.f32 "
        "{%0,%1,%2,%3},{%4,%5,%6,%7},{%8,%9},{%0,%1,%2,%3};"
        : "+f"(c[0]), "+f"(c[1]), "+f"(c[2]), "+f"(c[3])
        : "r"(a[0]), "r"(a[1]), "r"(a[2]), "r"(a[3]), "r"(b0), "r"(b1));
}

__device__ __forceinline__ void split2(float2 v, __nv_bfloat162& h, __nv_bfloat162& l) {
    h = __float22bfloat162_rn(v);
    float2 r = make_float2(v.x - __bfloat162float(h.x), v.y - __bfloat162float(h.y));
    l = __float22bfloat162_rn(r);
}
__device__ __forceinline__ void stage8(__nv_bfloat16* dh, __nv_bfloat16* dl,
                                       float4 f0, float4 f1) {
    __nv_bfloat162 h[4], l[4];
    split2(make_float2(f0.x, f0.y), h[0], l[0]);
    split2(make_float2(f0.z, f0.w), h[1], l[1]);
    split2(make_float2(f1.x, f1.y), h[2], l[2]);
    split2(make_float2(f1.z, f1.w), h[3], l[3]);
    *(uint4*)dh = *(uint4*)h;
    *(uint4*)dl = *(uint4*)l;
}

// ---------------- BK=32 smem geometry (dynamic smem) -------------------------
#define APX 40          // A pitch in halfs (80B rows -> conflict-free ldmatrix)
#define BPX 136         // B pitch in halfs (272B rows -> conflict-free trans)
#define AH_SZ (2*64*APX)       // per-field elems, 2 buffers
#define BH_SZ (2*32*BPX)
#define SMEM_BYTES ((2*AH_SZ + 2*BH_SZ) * 2)   // 55296 B

// one k16 substep (ks in {0,1}); warp layout wm:{0,1} x wn:{0..3}, NF=4
__device__ __forceinline__ void stepX(
    const __nv_bfloat16* Ah, const __nv_bfloat16* Al,
    const __nv_bfloat16* Bh, const __nv_bfloat16* Bl,
    int ks, int wm, int wn, int lane, float (*acc)[4])
{
    uint32_t ah[2][4], al[2][4];
    const int arow = lane & 15, acol = (lane >> 4) * 8;
    #pragma unroll
    for (int mf = 0; mf < 2; mf++) {
        int off = (wm * 32 + mf * 16 + arow) * APX + ks * 16 + acol;
        ldm_x4(ah[mf], smem_u32(Ah + off));
        ldm_x4(al[mf], smem_u32(Al + off));
    }
    const int bkr = lane & 15;
    const int bnl = (lane >> 4) * 8;
    #pragma unroll
    for (int nf2 = 0; nf2 < 2; nf2++) {
        int off = (ks * 16 + bkr) * BPX + wn * 32 + nf2 * 16 + bnl;
        uint32_t bh[4], bl4[4];
        ldm_x4t(bh,  smem_u32(Bh + off));
        ldm_x4t(bl4, smem_u32(Bl + off));
        #pragma unroll
        for (int mf = 0; mf < 2; mf++) {
            float* c0 = acc[mf * 4 + nf2 * 2 + 0];
            float* c1 = acc[mf * 4 + nf2 * 2 + 1];
            mma_bf16(c0, ah[mf], bh[0],  bh[1]);
            mma_bf16(c0, ah[mf], bl4[0], bl4[1]);
            mma_bf16(c0, al[mf], bh[0],  bh[1]);
            mma_bf16(c1, ah[mf], bh[2],  bh[3]);
            mma_bf16(c1, ah[mf], bl4[2], bl4[3]);
            mma_bf16(c1, al[mf], bh[2],  bh[3]);
        }
    }
}

#define GEMM_PREAMBLE \
    extern __shared__ __nv_bfloat16 dsm[]; \
    __nv_bfloat16* sAh = dsm; \
    __nv_bfloat16* sAl = dsm + AH_SZ; \
    __nv_bfloat16* sBh = dsm + 2 * AH_SZ; \
    __nv_bfloat16* sBl = dsm + 2 * AH_SZ + BH_SZ; \
    const int tid = threadIdx.x, lane = tid & 31, wid = tid >> 5; \
    const int wm = wid & 1, wn = wid >> 1; \
    const int ar = tid >> 2, akc = (tid & 3) * 8; \
    const int bk = tid >> 4, bnc = (tid & 15) * 8; \
    float acc[8][4]; \
    _Pragma("unroll") for (int i = 0; i < 8; i++) \
        _Pragma("unroll") for (int j = 0; j < 4; j++) acc[i][j] = 0.f;

#define A_AT(buf, r, c) (sAh + (buf) * (64 * APX) + (r) * APX + (c))
#define AL_AT(buf, r, c) (sAl + (buf) * (64 * APX) + (r) * APX + (c))
#define B_AT(buf, r, c) (sBh + (buf) * (32 * BPX) + (r) * BPX + (c))
#define BL_AT(buf, r, c) (sBl + (buf) * (32 * BPX) + (r) * BPX + (c))

#define STORE_STAGE(buf) \
    stage8(A_AT(buf, ar, akc), AL_AT(buf, ar, akc), fa0, fa1); \
    stage8(B_AT(buf, bk, bnc), BL_AT(buf, bk, bnc), fb0, fb1); \
    stage8(B_AT(buf, bk + 16, bnc), BL_AT(buf, bk + 16, bnc), fb2, fb3);

#define LOAD_B(k0) \
    fb0 = *(const float4*)(Bg + (size_t)(k0) * N); \
    fb1 = *(const float4*)(Bg + (size_t)(k0) * N + 4); \
    fb2 = *(const float4*)(Bg + (size_t)((k0) + 16) * N); \
    fb3 = *(const float4*)(Bg + (size_t)((k0) + 16) * N + 4);

#define MAINLOOP(LOAD_A) \
    __syncthreads(); \
    const int nK = Kd >> 5; \
    int buf = 0; \
    for (int kt = 0; kt < nK; kt++) { \
        const bool nxt = (kt + 1) < nK; \
        if (nxt) { int k0 = (kt + 1) << 5; LOAD_A(k0); LOAD_B(k0); } \
        stepX(A_AT(buf,0,0), AL_AT(buf,0,0), B_AT(buf,0,0), BL_AT(buf,0,0), 0, wm, wn, lane, acc); \
        stepX(A_AT(buf,0,0), AL_AT(buf,0,0), B_AT(buf,0,0), BL_AT(buf,0,0), 1, wm, wn, lane, acc); \
        if (nxt) { int nb = buf ^ 1; STORE_STAGE(nb); } \
        __syncthreads(); \
        buf ^= 1; \
    }

// ============================================================================
// Batched dense GEMM: C[z] = A @ B[z]. BM=64, BN=128, BK=32.
// ============================================================================
#define LOADA_PLAIN(k0) \
    fa0 = *(const float4*)(Ag + (k0)); fa1 = *(const float4*)(Ag + (k0) + 4);

__global__ __launch_bounds__(256)
void mma_d64_batch(const float* __restrict__ A, const float* __restrict__ Bw,
                   float* __restrict__ C, int Kd, int N,
                   size_t bStride, size_t cStride)
{
    GEMM_PREAMBLE
    const int m0 = blockIdx.y * 64, n0 = blockIdx.x * 128;
    const float* Bz = Bw + (size_t)blockIdx.z * bStride;
    float* Cz = C + (size_t)blockIdx.z * cStride;
    const float* Ag = A + (size_t)(m0 + ar) * Kd + akc;
    const float* Bg = Bz + (size_t)bk * N + n0 + bnc;

    float4 fa0, fa1, fb0, fb1, fb2, fb3;
    LOADA_PLAIN(0) LOAD_B(0) STORE_STAGE(0)
    MAINLOOP(LOADA_PLAIN)

    #pragma unroll
    for (int mf = 0; mf < 2; mf++)
        #pragma unroll
        for (int nf = 0; nf < 4; nf++) {
            float* c = acc[mf * 4 + nf];
            int r0  = m0 + wm * 32 + mf * 16 + (lane >> 2);
            int col = n0 + wn * 32 + nf * 8 + (lane & 3) * 2;
            float* p0 = Cz + (size_t)r0 * N + col;
            float* p1 = Cz + (size_t)(r0 + 8) * N + col;
            p0[0] = c[0]; p0[1] = c[1]; p1[0] = c[2]; p1[1] = c[3];
        }
}

// ============================================================================
// Split-K dense GEMM (Wo): z halves K, partials to C + z*T*H.
// ============================================================================
__global__ __launch_bounds__(256)
void mma_d64_splitk(const float* __restrict__ A, const float* __restrict__ Bw,
                    float* __restrict__ C, int KdFull, int N)
{
    GEMM_PREAMBLE
    const int m0 = blockIdx.y * 64, n0 = blockIdx.x * 128;
    const int Kd = KdFull >> 1;
    const int kOff = blockIdx.z * Kd;
    float* Cz = C + (size_t)blockIdx.z * T_ * H_;
    const float* Ag = A + (size_t)(m0 + ar) * KdFull + kOff + akc;
    const float* Bg = Bw + (size_t)(kOff + bk) * N + n0 + bnc;

    float4 fa0, fa1, fb0, fb1, fb2, fb3;
    LOADA_PLAIN(0) LOAD_B(0) STORE_STAGE(0)
    MAINLOOP(LOADA_PLAIN)

    #pragma unroll
    for (int mf = 0; mf < 2; mf++)
        #pragma unroll
        for (int nf = 0; nf < 4; nf++) {
            float* c = acc[mf * 4 + nf];
            int r0  = m0 + wm * 32 + mf * 16 + (lane >> 2);
            int col = n0 + wn * 32 + nf * 8 + (lane & 3) * 2;
            float* p0 = Cz + (size_t)r0 * N + col;
            float* p1 = Cz + (size_t)(r0 + 8) * N + col;
            p0[0] = c[0]; p0[1] = c[1]; p1[0] = c[2]; p1[1] = c[3];
        }
}

// ============================================================================
// Shared-expert down GEMM (fused SwiGLU A), batched over z=e.
// ============================================================================
#define LOADA_SWI(k0) { \
    float4 gg0 = *(const float4*)(Gg + (k0)), gg1 = *(const float4*)(Gg + (k0) + 4); \
    float4 uu0 = *(const float4*)(Gg + (k0) + I_), uu1 = *(const float4*)(Gg + (k0) + I_ + 4); \
    fa0 = make_float4(silu1(gg0.x)*uu0.x, silu1(gg0.y)*uu0.y, silu1(gg0.z)*uu0.z, silu1(gg0.w)*uu0.w); \
    fa1 = make_float4(silu1(gg1.x)*uu1.x, silu1(gg1.y)*uu1.y, silu1(gg1.z)*uu1.z, silu1(gg1.w)*uu1.w); }

__global__ __launch_bounds__(256)
void mma_shared_down(const float* __restrict__ Wd_s)
{
    GEMM_PREAMBLE
    const int N = H_, Kd = I_;
    const int m0 = blockIdx.y * 64, n0 = blockIdx.x * 128;
    const int e = blockIdx.z;
    const float* Gg = g_sgu + (size_t)e * T_ * 2 * I_ + (size_t)(m0 + ar) * (2 * I_) + akc;
    const float* Bg = Wd_s + (size_t)e * I_ * H_ + (size_t)bk * N + n0 + bnc;
    float* Cz = g_sdwn + (size_t)e * T_ * H_;

    float4 fa0, fa1, fb0, fb1, fb2, fb3;
    LOADA_SWI(0) LOAD_B(0) STORE_STAGE(0)
    MAINLOOP(LOADA_SWI)

    #pragma unroll
    for (int mf = 0; mf < 2; mf++)
        #pragma unroll
        for (int nf = 0; nf < 4; nf++) {
            float* c = acc[mf * 4 + nf];
            int r0  = m0 + wm * 32 + mf * 16 + (lane >> 2);
            int col = n0 + wn * 32 + nf * 8 + (lane & 3) * 2;
            float* p0 = Cz + (size_t)r0 * N + col;
            float* p1 = Cz + (size_t)(r0 + 8) * N + col;
            p0[0] = c[0]; p0[1] = c[1]; p1[0] = c[2]; p1[1] = c[3];
        }
}

// ============================================================================
// Routed up GEMM: gathered A rows from g_h1. grid=(2I/128, T/64, E).
// ============================================================================
#define LOADA_GATH(k0) \
    fa0 = (tok >= 0) ? *(const float4*)(Ag + (k0)) : make_float4(0.f,0.f,0.f,0.f); \
    fa1 = (tok >= 0) ? *(const float4*)(Ag + (k0) + 4) : make_float4(0.f,0.f,0.f,0.f);

__global__ __launch_bounds__(256)
void mma_up_routed(const float* __restrict__ Wgu)
{
    const int e = blockIdx.z;
    const int cnt = g_cnt[e];
    const int m0 = blockIdx.y * 64;
    if (m0 >= cnt) return;
    GEMM_PREAMBLE
    const int off = g_off[e];
    const int n0 = blockIdx.x * 128;
    const int N = 2 * I_, Kd = H_;
    const int tok = (m0 + ar < cnt) ? g_ltok[off + m0 + ar] : -1;
    const float* Ag = (tok >= 0) ? (g_h1 + (size_t)tok * H_ + akc) : g_h1;
    const float* Bg = Wgu + (size_t)e * H_ * 2 * I_ + (size_t)bk * N + n0 + bnc;

    float4 fa0, fa1, fb0, fb1, fb2, fb3;
    LOADA_GATH(0) LOAD_B(0) STORE_STAGE(0)
    MAINLOOP(LOADA_GATH)

    #pragma unroll
    for (int mf = 0; mf < 2; mf++)
        #pragma unroll
        for (int nf = 0; nf < 4; nf++) {
            float* c = acc[mf * 4 + nf];
            int lr0 = m0 + wm * 32 + mf * 16 + (lane >> 2);
            int col = n0 + wn * 32 + nf * 8 + (lane & 3) * 2;
            if (lr0 < cnt) {
                float* p = g_rgu + (size_t)(off + lr0) * N + col;
                p[0] = c[0]; p[1] = c[1];
            }
            if (lr0 + 8 < cnt) {
                float* p = g_rgu + (size_t)(off + lr0 + 8) * N + col;
                p[0] = c[2]; p[1] = c[3];
            }
        }
}

// ============================================================================
// Routed down GEMM: fused SwiGLU A from g_rgu, weighted scatter epilogue.
// ============================================================================
#define LOADA_SWIR(k0) \
    if (aok) { \
        float4 gg0 = *(const float4*)(Ag + (k0)), gg1 = *(const float4*)(Ag + (k0) + 4); \
        float4 uu0 = *(const float4*)(Ag + (k0) + I_), uu1 = *(const float4*)(Ag + (k0) + I_ + 4); \
        fa0 = make_float4(silu1(gg0.x)*uu0.x, silu1(gg0.y)*uu0.y, silu1(gg0.z)*uu0.z, silu1(gg0.w)*uu0.w); \
        fa1 = make_float4(silu1(gg1.x)*uu1.x, silu1(gg1.y)*uu1.y, silu1(gg1.z)*uu1.z, silu1(gg1.w)*uu1.w); \
    } else { fa0 = fa1 = make_float4(0.f,0.f,0.f,0.f); }

__global__ __launch_bounds__(256)
void mma_down_routed(const float* __restrict__ Wd)
{
    const int e = blockIdx.z;
    const int cnt = g_cnt[e];
    const int m0 = blockIdx.y * 64;
    if (m0 >= cnt) return;
    GEMM_PREAMBLE
    const int off = g_off[e];
    const int n0 = blockIdx.x * 128;
    const int N = H_, Kd = I_;
    const bool aok = (m0 + ar) < cnt;
    const float* Ag = g_rgu + (size_t)(off + (aok ? m0 + ar : 0)) * (2 * I_) + akc;
    const float* Bg = Wd + (size_t)e * I_ * H_ + (size_t)bk * N + n0 + bnc;

    float4 fa0, fa1, fb0, fb1, fb2, fb3;
    LOADA_SWIR(0) LOAD_B(0) STORE_STAGE(0)
    MAINLOOP(LOADA_SWIR)

    #pragma unroll
    for (int mf = 0; mf < 2; mf++)
        #pragma unroll
        for (int nf = 0; nf < 4; nf++) {
            float* c = acc[mf * 4 + nf];
            int lr0 = m0 + wm * 32 + mf * 16 + (lane >> 2);
            int col = n0 + wn * 32 + nf * 8 + (lane & 3) * 2;
            if (lr0 < cnt) {
                int slot = g_lslot[off + lr0];
                float w  = g_lw[off + lr0];
                float* p = g_rdwn + (size_t)slot * H_ + col;
                p[0] = w * c[0]; p[1] = w * c[1];
            }
            if (lr0 + 8 < cnt) {
                int slot = g_lslot[off + lr0 + 8];
                float w  = g_lw[off + lr0 + 8];
                float* p = g_rdwn + (size_t)slot * H_ + col;
                p[0] = w * c[2]; p[1] = w * c[3];
            }
        }
}

// ---------------- flash attention (fp32, validated) --------------------------
__global__ __launch_bounds__(256)
void flash_attn() {
    __shared__ float Qs[64][68];
    __shared__ float Ks[32][68];
    __shared__ float Vs[32][68];
    __shared__ float Ps[64][36];
    const int q0 = blockIdx.x * 64;
    const int h  = blockIdx.y;
    const int b  = blockIdx.z;
    const int tid = threadIdx.x;
    const size_t rs = 3 * H_;
    const float* qb = g_qkv + (size_t)b * S_ * rs + (size_t)h * HD_;
    const float* kb = qb + H_;
    const float* vb = qb + 2 * H_;
    const float scale = 0.125f;
    for (int i = tid; i < 64 * 64; i += 256) {
        int r = i >> 6, d = i & 63;
        Qs[r][d] = qb[(size_t)(q0 + r) * rs + d] * scale;
    }
    const int r  = tid >> 2;
    const int c4 = tid & 3;
    float m_i = -1e30f, l_i = 0.f;
    float acc[16];
    #pragma unroll
    for (int i = 0; i < 16; i++) acc[i] = 0.f;
    __syncthreads();
    for (int kt = 0; kt < S_; kt += 32) {
        for (int i = tid; i < 32 * 64; i += 256) {
            int rr = i >> 6, d = i & 63;
            Ks[rr][d] = kb[(size_t)(kt + rr) * rs + d];
            Vs[rr][d] = vb[(size_t)(kt + rr) * rs + d];
        }
        __syncthreads();
        float sc[8];
        float mx = -1e30f;
        const float4* qrow = (const float4*)&Qs[r][0];
        #pragma unroll
        for (int jj = 0; jj < 8; jj++) {
            int j = c4 * 8 + jj;
            const float4* krow = (const float4*)&Ks[j][0];
            float sv = 0.f;
            #pragma unroll
            for (int dv = 0; dv < 16; dv++) {
                float4 a = qrow[dv], bq = krow[dv];
                sv += a.x * bq.x + a.y * bq.y + a.z * bq.z + a.w * bq.w;
            }
            sc[jj] = sv; mx = fmaxf(mx, sv);
        }
        mx = fmaxf(mx, __shfl_xor_sync(0xffffffffu, mx, 1));
        mx = fmaxf(mx, __shfl_xor_sync(0xffffffffu, mx, 2));
        float m_new = fmaxf(m_i, mx);
        float alpha = expf(m_i - m_new);
        float psum = 0.f;
        #pragma unroll
        for (int jj = 0; jj < 8; jj++) {
            float p = expf(sc[jj] - m_new);
            Ps[r][c4 * 8 + jj] = p;
            psum += p;
        }
        psum += __shfl_xor_sync(0xffffffffu, psum, 1);
        psum += __shfl_xor_sync(0xffffffffu, psum, 2);
        l_i = l_i * alpha + psum;
        m_i = m_new;
        #pragma unroll
        for (int i = 0; i < 16; i++) acc[i] *= alpha;
        __syncwarp();
        #pragma unroll
        for (int i = 0; i < 16; i++) {
            int d = c4 * 16 + i;
            float s = 0.f;
            #pragma unroll 8
            for (int j = 0; j < 32; j++) s += Ps[r][j] * Vs[j][d];
            acc[i] += s;
        }
        __syncthreads();
    }
    float inv = 1.f / l_i;
    float* ob = g_attn + (size_t)((b * S_ + q0 + r)) * H_ + (size_t)h * HD_;
    #pragma unroll
    for (int i = 0; i < 16; i++) ob[c4 * 16 + i] = acc[i] * inv;
}

// ---------------- residual + rmsnorm over 3-way sum --------------------------
__global__ __launch_bounds__(256)
void resid_rms3(const float* __restrict__ a, const float* __restrict__ b0,
                const float* __restrict__ b1, float* __restrict__ o) {
    const int t = blockIdx.x;
    float v[4]; float ss = 0.f;
    #pragma unroll
    for (int i = 0; i < 4; i++) {
        int j = i * 256 + threadIdx.x;
        float s = a[(size_t)t * H_ + j] + b0[(size_t)t * H_ + j] + b1[(size_t)t * H_ + j];
        v[i] = s; ss += s * s;
    }
    ss = block_sum256(ss);
    float inv = rsqrtf(ss * (1.f / H_) + EPS_);
    #pragma unroll
    for (int i = 0; i < 4; i++) {
        int j = i * 256 + threadIdx.x;
        o[(size_t)t * H_ + j] = v[i] * inv;
    }
}

// ---------------- routing ---------------------------------------------------
__global__ void zero_small() {
    int i = threadIdx.x;
    if (i < E_) { g_Pi[i] = 0.f; g_cnt[i] = 0; }
    if (i < D_)   g_comm[i] = 0.f;
}

__global__ void routing_kernel(const float* __restrict__ Wr) {
    const int t = blockIdx.x;
    const int e = threadIdx.x;   // 32 threads
    const float* xr = g_h1 + (size_t)t * H_;
    float logit = 0.f;
    for (int j = 0; j < H_; j++) logit += xr[j] * Wr[(size_t)j * E_ + e];
    float m = logit;
    #pragma unroll
    for (int o = 16; o; o >>= 1) m = fmaxf(m, __shfl_xor_sync(0xffffffffu, m, o));
    float ex = expf(logit - m);
    float s = ex;
    #pragma unroll
    for (int o = 16; o; o >>= 1) s += __shfl_xor_sync(0xffffffffu, s, o);
    float prob = ex / s;
    atomicAdd(&g_Pi[e], prob);
    __shared__ float sp[E_];
    sp[e] = prob;
    __syncwarp();
    if (e == 0) {
        float ds[D_];
        #pragma unroll
        for (int d = 0; d < D_; d++)
            ds[d] = sp[4 * d] + sp[4 * d + 1] + sp[4 * d + 2] + sp[4 * d + 3];
        bool dsel[D_] = {};
        for (int rsel = 0; rsel < KD_; rsel++) {
            int best = -1; float bv = -1e30f;
            for (int d = 0; d < D_; d++)
                if (!dsel[d] && ds[d] > bv) { bv = ds[d]; best = d; }
            dsel[best] = true;
        }
        float masked[E_];
        #pragma unroll
        for (int i = 0; i < E_; i++)
            masked[i] = dsel[i >> 2] ? sp[i] : -1e30f;
        int   iv[K_]; float wv[K_];
        for (int rsel = 0; rsel < K_; rsel++) {
            int best = 0; float bv = -1e31f;
            for (int i = 0; i < E_; i++)
                if (masked[i] > bv) { bv = masked[i]; best = i; }
            iv[rsel] = best; wv[rsel] = bv;
            masked[best] = -1e31f;
        }
        float mm = wv[0];
        float ssum = 0.f;
        #pragma unroll
        for (int rsel = 0; rsel < K_; rsel++) { wv[rsel] = expf(wv[rsel] - mm); ssum += wv[rsel]; }
        bool hit[D_] = {};
        #pragma unroll
        for (int rsel = 0; rsel < K_; rsel++) hit[iv[rsel] >> 2] = true;
        for (int d = 0; d < D_; d++)
            if (hit[d]) atomicAdd(&g_comm[d], 1.0f);
        #pragma unroll
        for (int rsel = 0; rsel < K_; rsel++) {
            int idx = t * K_ + rsel;
            g_sel_e[idx] = iv[rsel];
            g_sel_w[idx] = wv[rsel] / ssum;
            atomicAdd(&g_cnt[iv[rsel]], 1);
        }
    }
}

__global__ void offsets_kernel() {
    if (threadIdx.x == 0) {
        int s = 0;
        for (int e = 0; e < E_; e++) { g_off[e] = s; g_cur[e] = s; s += g_cnt[e]; }
    }
}

__global__ void scatter_kernel() {
    int i = blockIdx.x * 256 + threadIdx.x;
    if (i >= TK_) return;
    int e = g_sel_e[i];
    int pos = atomicAdd(&g_cur[e], 1);
    g_ltok[pos]  = i / K_;
    g_lslot[pos] = i;
    g_lw[pos]    = g_sel_w[i];
}

// ---------------- final combine + rmsnorm + aux ------------------------------
__global__ __launch_bounds__(256)
void final_kernel(float* __restrict__ out) {
    const int t = blockIdx.x;
    float v[4]; float ss = 0.f;
    #pragma unroll
    for (int i = 0; i < 4; i++) {
        int j = i * 256 + threadIdx.x;
        float s = g_h1[(size_t)t * H_ + j]
                + g_sdwn[(size_t)t * H_ + j]
                + g_sdwn[(size_t)(T_ + t) * H_ + j];
        #pragma unroll
        for (int k = 0; k < K_; k++)
            s += g_rdwn[(size_t)(t * K_ + k) * H_ + j];
        v[i] = s; ss += s * s;
    }
    ss = block_sum256(ss);
    float inv = rsqrtf(ss * (1.f / H_) + EPS_);
    #pragma unroll
    for (int i = 0; i < 4; i++) {
        int j = i * 256 + threadIdx.x;
        out[(size_t)t * H_ + j] = v[i] * inv;
    }
}

__global__ void aux_kernel(float* out, int out_size) {
    if (out_size <= T_ * H_) return;
    const float fTK = (float)TK_ + 1e-10f;
    float fi[E_], Pi[E_];
    float s1 = 0.f;
    for (int e = 0; e < E_; e++) {
        fi[e] = (float)g_cnt[e] / fTK;
        Pi[e] = g_Pi[e] / (float)T_;
        s1 += fi[e] * Pi[e];
    }
    float eb = fminf(s1 * 0.003f, 10.f);
    float dP[D_];
    float s2 = 0.f;
    for (int d = 0; d < D_; d++) {
        float df = (fi[4*d] + fi[4*d+1] + fi[4*d+2] + fi[4*d+3]) * 0.25f;
        dP[d]    = Pi[4*d] + Pi[4*d+1] + Pi[4*d+2] + Pi[4*d+3];
        s2 += df * dP[d];
    }
    float db = fminf(s2 * 0.05f, 10.f);
    float s3 = 0.f;
    for (int d = 0; d < D_; d++) {
        float fc = g_comm[d] / ((float)(T_ * KD_) + 1e-10f);
        s3 += fc * dP[d];
    }
    float cb = fminf(s3 * 0.02f, 10.f);
    out[T_ * H_] = eb + db + cb;
}

// ---------------- host driver ------------------------------------------------
extern "C" void kernel_launch(void* const* d_in, const int* in_sizes, int n_in,
                              void* d_out, int out_size) {
    const float* x     = (const float*)d_in[0];
    const float* Wqkv  = (const float*)d_in[1];
    const float* Wo    = (const float*)d_in[2];
    const float* Wgu_s = (const float*)d_in[3];
    const float* Wd_s  = (const float*)d_in[4];
    const float* Wr    = (const float*)d_in[5];
    const float* Wgu   = (const float*)d_in[6];
    const float* Wd    = (const float*)d_in[7];
    float* out = (float*)d_out;

    float *p_qkv, *p_attn, *p_tmp, *p_h1, *p_sgu;
    cudaGetSymbolAddress((void**)&p_qkv,  g_qkv);
    cudaGetSymbolAddress((void**)&p_attn, g_attn);
    cudaGetSymbolAddress((void**)&p_tmp,  g_tmp);
    cudaGetSymbolAddress((void**)&p_h1,   g_h1);
    cudaGetSymbolAddress((void**)&p_sgu,  g_sgu);

    // one-time: opt-in smem + side stream/events (created on the uncaptured
    // correctness call; reused under capture)
    static bool init_done = false;
    static cudaStream_t s1;
    static cudaEvent_t evFork, evJoin;
    if (!init_done) {
        cudaFuncSetAttribute(mma_d64_batch,   cudaFuncAttributeMaxDynamicSharedMemorySize, SMEM_BYTES);
        cudaFuncSetAttribute(mma_d64_splitk,  cudaFuncAttributeMaxDynamicSharedMemorySize, SMEM_BYTES);
        cudaFuncSetAttribute(mma_shared_down, cudaFuncAttributeMaxDynamicSharedMemorySize, SMEM_BYTES);
        cudaFuncSetAttribute(mma_up_routed,   cudaFuncAttributeMaxDynamicSharedMemorySize, SMEM_BYTES);
        cudaFuncSetAttribute(mma_down_routed, cudaFuncAttributeMaxDynamicSharedMemorySize, SMEM_BYTES);
        cudaStreamCreateWithFlags(&s1, cudaStreamNonBlocking);
        cudaEventCreateWithFlags(&evFork, cudaEventDisableTiming);
        cudaEventCreateWithFlags(&evJoin, cudaEventDisableTiming);
        init_done = true;
    }

    zero_small<<<1, 64>>>();

    // qkv = x @ Wqkv
    mma_d64_batch<<<dim3(3 * H_ / 128, T_ / 64, 1), 256, SMEM_BYTES>>>(
        x, Wqkv, p_qkv, H_, 3 * H_, 0, 0);

    // attention
    flash_attn<<<dim3(S_ / 64, NH_, B_), 256>>>();

    // Wo split-K=2 ; h1 = rmsnorm(x + tmp0 + tmp1)
    mma_d64_splitk<<<dim3(H_ / 128, T_ / 64, 2), 256, SMEM_BYTES>>>(
        p_attn, Wo, p_tmp, H_, H_);
    resid_rms3<<<T_, 256>>>(x, p_tmp, p_tmp + (size_t)T_ * H_, p_h1);

    // fork: shared-expert chain on s1, routed chain on main stream
    cudaEventRecord(evFork, 0);
    cudaStreamWaitEvent(s1, evFork, 0);

    mma_d64_batch<<<dim3(2 * I_ / 128, T_ / 64, 2), 256, SMEM_BYTES, s1>>>(
        p_h1, Wgu_s, p_sgu, H_, 2 * I_,
        (size_t)H_ * 2 * I_, (size_t)T_ * 2 * I_);
    mma_shared_down<<<dim3(H_ / 128, T_ / 64, 2), 256, SMEM_BYTES, s1>>>(Wd_s);
    cudaEventRecord(evJoin, s1);

    routing_kernel<<<T_, 32>>>(Wr);
    offsets_kernel<<<1, 32>>>();
    scatter_kernel<<<(TK_ + 255) / 256, 256>>>();
    mma_up_routed<<<dim3(2 * I_ / 128, T_ / 64, E_), 256, SMEM_BYTES>>>(Wgu);
    mma_down_routed<<<dim3(H_ / 128, T_ / 64, E_), 256, SMEM_BYTES>>>(Wd);

    // join and finish
    cudaStreamWaitEvent(0, evJoin, 0);
    final_kernel<<<T_, 256>>>(out);
    aux_kernel<<<1, 1>>>(out, out_size);
}